// round 7
// baseline (speedup 1.0000x reference)
#include <cuda_runtime.h>
#include <cuda_fp16.h>
#include <cstdint>
#include <math.h>

#define Bk 8
#define Lk 2048
#define Dk 2048
#define Rk 256
#define BLk (Bk * Lk)   // 16384 rows

// ---------------- device scratch ----------------
static __device__ float g_C[Rk * Rk];                 // Toeplitz matrix C[s,i]
static __device__ float g_E[Rk * Rk];                 // E = C @ dlt       (256x256)
static __device__ __half g_BT1[Rk * Dk];              // A'^T fp16         (256x2048)
static __device__ __half g_WqT[Dk * Rk];              // Wq^T fp16         (2048x256)
static __device__ __half g_Xh[(size_t)BLk * Dk];      // X in fp16 (64MB)
static __device__ float g_rstd[BLk], g_nmr[BLk];
static __device__ float g_feat[BLk];
static __device__ float g_pg[Rk], g_pb[Rk];
static __device__ float g_cA[Rk], g_cB[Rk];
static __device__ float g_G[Dk];
static __device__ float g_consts[4];
static __device__ float g_pgp[32 * Rk], g_pbp[32 * Rk];

// ---------------- helpers ----------------
__device__ __forceinline__ uint32_t smem_u32(const void* p) {
    uint32_t a;
    asm("{ .reg .u64 t; cvta.to.shared.u64 t, %1; cvt.u32.u64 %0, t; }" : "=r"(a) : "l"(p));
    return a;
}
__device__ __forceinline__ void cp16(void* dst, const void* src) {
    uint32_t d = smem_u32(dst);
    asm volatile("cp.async.cg.shared.global [%0], [%1], 16;" :: "r"(d), "l"(src) : "memory");
}
#define CP_COMMIT() asm volatile("cp.async.commit_group;" ::: "memory")
#define CP_WAIT0()  asm volatile("cp.async.wait_group 0;" ::: "memory")

#define LDSM4(r0, r1, r2, r3, addr) \
    asm volatile("ldmatrix.sync.aligned.m8n8.x4.shared.b16 {%0,%1,%2,%3}, [%4];" \
        : "=r"(r0), "=r"(r1), "=r"(r2), "=r"(r3) : "r"(addr))

#define MMAF16(c, a, b) \
    asm volatile( \
        "mma.sync.aligned.m16n8k16.row.col.f32.f16.f16.f32 " \
        "{%0,%1,%2,%3},{%4,%5,%6,%7},{%8,%9},{%0,%1,%2,%3};" \
        : "+f"((c)[0]), "+f"((c)[1]), "+f"((c)[2]), "+f"((c)[3]) \
        : "r"((a)[0]), "r"((a)[1]), "r"((a)[2]), "r"((a)[3]), \
          "r"((b)[0]), "r"((b)[1]))

__device__ __forceinline__ uint32_t h2pack(float a, float b) {
    __half2 h = __floats2half2_rn(a, b);
    return *reinterpret_cast<uint32_t*>(&h);
}

__device__ __forceinline__ float blockReduce256(float v, float* sm) {
    int t = threadIdx.x;
    sm[t] = v;
    __syncthreads();
    #pragma unroll
    for (int off = 128; off > 0; off >>= 1) {
        if (t < off) sm[t] += sm[t + off];
        __syncthreads();
    }
    float r = sm[0];
    __syncthreads();
    return r;
}

// ================= fused precompute 1 =================
__global__ __launch_bounds__(256) void kPre1(const float* __restrict__ gamma,
                                             const float* __restrict__ beta,
                                             const float* __restrict__ phiw,
                                             const float* __restrict__ P,
                                             const float* __restrict__ toep,
                                             const float* __restrict__ Wq, int Kc) {
    int bid = blockIdx.x, t = threadIdx.x;
    if (bid == 0) {
        __shared__ float sm[256];
        float a = 0.f, b = 0.f, c = 0.f;
        for (int j = t; j < Dk; j += 256) { a += gamma[j]; b += beta[j]; }
        for (int j = t; j < Rk; j += 256) { c += phiw[j]; }
        float A = blockReduce256(a, sm);
        float B = blockReduce256(b, sm);
        float C = blockReduce256(c, sm);
        if (t == 0) { g_consts[0] = A; g_consts[1] = B; g_consts[2] = C; }
    } else if (bid <= 32) {
        int chunk = bid - 1;
        float ag = 0.f, ab = 0.f;
        #pragma unroll 4
        for (int j = 0; j < 64; j++) {
            int d = chunk * 64 + j;
            float p = P[(size_t)d * Rk + t];
            ag += gamma[d] * p;
            ab += beta[d] * p;
        }
        g_pgp[chunk * Rk + t] = ag;
        g_pbp[chunk * Rk + t] = ab;
    } else if (bid <= 288) {
        int s = bid - 33;
        int pad = (Kc - 1) >> 1;
        int idx = t - s + pad;
        g_C[s * Rk + t] = (idx >= 0 && idx < Kc) ? toep[idx] : 0.f;
    } else {
        int id = bid - 289;
        int bx = id & 63, by = id >> 6;
        __shared__ float tile[32][33];
        int tx = t & 31, ty8 = t >> 5;
        #pragma unroll
        for (int i = 0; i < 32; i += 8)
            tile[ty8 + i][tx] = Wq[(size_t)(by * 32 + ty8 + i) * Dk + bx * 32 + tx];
        __syncthreads();
        #pragma unroll
        for (int i = 0; i < 32; i += 8)
            g_WqT[(size_t)(bx * 32 + ty8 + i) * Rk + by * 32 + tx] =
                __float2half_rn(tile[tx][ty8 + i]);
    }
}

// ================= kEg: E = C @ dlt + pgb2 reduce =================
__global__ __launch_bounds__(256) void kEg(const float* __restrict__ dlt) {
    int bid = blockIdx.x, t = threadIdx.x;
    if (bid == 16) {
        float a = 0.f, b = 0.f;
        #pragma unroll
        for (int c = 0; c < 32; c++) { a += g_pgp[c * Rk + t]; b += g_pbp[c * Rk + t]; }
        g_pg[t] = a;
        g_pb[t] = b;
        return;
    }
    __shared__ float Cs[16][66];
    __shared__ float Ds[16][68];
    int bx = bid & 3, by = bid >> 2;
    int sBase = by * 64, rBase = bx * 64;
    int ty = t >> 4, tx = t & 15;
    float acc[4][4] = {};
    for (int k0 = 0; k0 < Rk; k0 += 16) {
        {
            int m = t >> 2, kq = (t & 3) * 4;
            float4 v = *(const float4*)&g_C[(size_t)(sBase + m) * Rk + k0 + kq];
            Cs[kq + 0][m] = v.x; Cs[kq + 1][m] = v.y; Cs[kq + 2][m] = v.z; Cs[kq + 3][m] = v.w;
        }
        {
            int kk = t >> 4, n4 = (t & 15) * 4;
            float4 v = *(const float4*)&dlt[(size_t)(k0 + kk) * Rk + rBase + n4];
            *(float4*)&Ds[kk][n4] = v;
        }
        __syncthreads();
        #pragma unroll
        for (int k = 0; k < 16; k++) {
            float a[4], b[4];
            #pragma unroll
            for (int i = 0; i < 4; i++) a[i] = Cs[k][ty * 4 + i];
            #pragma unroll
            for (int j = 0; j < 4; j++) b[j] = Ds[k][tx * 4 + j];
            #pragma unroll
            for (int i = 0; i < 4; i++)
                #pragma unroll
                for (int j = 0; j < 4; j++) acc[i][j] += a[i] * b[j];
        }
        __syncthreads();
    }
    #pragma unroll
    for (int i = 0; i < 4; i++)
        #pragma unroll
        for (int j = 0; j < 4; j++)
            g_E[(size_t)(sBase + ty * 4 + i) * Rk + rBase + tx * 4 + j] = acc[i][j];
}

// ================= kApCab =================
__global__ __launch_bounds__(256) void kApCab(const float* __restrict__ P,
                                              const float* __restrict__ gamma) {
    int bid = blockIdx.x, t = threadIdx.x;
    if (bid >= 128) {
        __shared__ float sm[256];
        int s = bid - 128;
        float e = g_E[(size_t)s * Rk + t];
        float ca = blockReduce256(g_pg[t] * e, sm);
        float cb = blockReduce256(g_pb[t] * e, sm);
        if (t == 0) { g_cA[s] = ca; g_cB[s] = cb; }
        return;
    }
    __shared__ float Ps[16][64];
    __shared__ float Es[16][64];
    int bx = bid & 3, by = bid >> 2;
    int dBase = by * 64, sBase = bx * 64;
    int ty = t >> 4, tx = t & 15;
    float acc[4][4] = {};
    for (int k0 = 0; k0 < Rk; k0 += 16) {
        {
            int m = t >> 2, kq = (t & 3) * 4;
            float4 v = *(const float4*)&P[(size_t)(dBase + m) * Rk + k0 + kq];
            Ps[kq + 0][m] = v.x; Ps[kq + 1][m] = v.y; Ps[kq + 2][m] = v.z; Ps[kq + 3][m] = v.w;
        }
        {
            int n = t >> 2, kq = (t & 3) * 4;
            float4 v = *(const float4*)&g_E[(size_t)(sBase + n) * Rk + k0 + kq];
            Es[kq + 0][n] = v.x; Es[kq + 1][n] = v.y; Es[kq + 2][n] = v.z; Es[kq + 3][n] = v.w;
        }
        __syncthreads();
        #pragma unroll
        for (int k = 0; k < 16; k++) {
            float a[4], b[4];
            #pragma unroll
            for (int i = 0; i < 4; i++) a[i] = Ps[k][ty * 4 + i];
            #pragma unroll
            for (int j = 0; j < 4; j++) b[j] = Es[k][tx * 4 + j];
            #pragma unroll
            for (int i = 0; i < 4; i++)
                #pragma unroll
                for (int j = 0; j < 4; j++) acc[i][j] += a[i] * b[j];
        }
        __syncthreads();
    }
    #pragma unroll
    for (int i = 0; i < 4; i++) {
        int d = dBase + ty * 4 + i;
        float g = gamma[d];
        #pragma unroll
        for (int j = 0; j < 4; j++) {
            int s = sBase + tx * 4 + j;
            g_BT1[(size_t)s * Dk + d] = __float2half_rn(g * acc[i][j]);
        }
    }
}

// ================= kStats: LN stats + fp16 conversion of X =================
// grid 2048, 256 thr (8 warps, warp per row).
__global__ __launch_bounds__(256) void kStats(const float* __restrict__ X,
                                              const float* __restrict__ gamma) {
    int w = threadIdx.x >> 5, lane = threadIdx.x & 31;
    int row = blockIdx.x * 8 + w;
    const float4* Xr = (const float4*)(X + (size_t)row * Dk);
    const float4* Gm = (const float4*)gamma;
    __half* Xo = g_Xh + (size_t)row * Dk;
    float s = 0.f, s2 = 0.f, sg = 0.f;
    #pragma unroll
    for (int j = 0; j < 16; j++) {
        int idx = j * 32 + lane;
        float4 v = Xr[idx];
        float4 gv = Gm[idx];
        s  += (v.x + v.y) + (v.z + v.w);
        s2 += v.x * v.x + v.y * v.y + v.z * v.z + v.w * v.w;
        sg += gv.x * v.x + gv.y * v.y + gv.z * v.z + gv.w * v.w;
        uint2 pk = { h2pack(v.x, v.y), h2pack(v.z, v.w) };
        *(uint2*)(Xo + idx * 4) = pk;
    }
    #pragma unroll
    for (int o = 16; o > 0; o >>= 1) {
        s  += __shfl_xor_sync(0xffffffffu, s, o);
        s2 += __shfl_xor_sync(0xffffffffu, s2, o);
        sg += __shfl_xor_sync(0xffffffffu, sg, o);
    }
    if (lane == 0) {
        float C0 = g_consts[0], C1 = g_consts[1];
        float mean = s * (1.f / Dk);
        float var = s2 * (1.f / Dk) - mean * mean;
        float rstd = rsqrtf(var + 1e-5f);
        g_rstd[row] = rstd;
        g_nmr[row] = -mean * rstd;
        g_feat[row] = (sg - mean * C0) * rstd * (1.f / Dk) + C1 * (1.f / Dk);
    }
}

// G[l] = sigmoid(g_logit[..]) * scale[l]
__global__ void kScale(const float* __restrict__ phib, const float* __restrict__ glog,
                       const int* __restrict__ step_p, int glen) {
    int w = threadIdx.x >> 5, lane = threadIdx.x & 31;
    int l = blockIdx.x * 8 + w;
    const float PI_F = 3.14159274101257324f;
    float base = PI_F * ((float)l + 0.5f);
    float c1 = 0.f, c2 = 0.f;
    #pragma unroll
    for (int j = 0; j < 8; j++) {
        int r = lane + 32 * j;
        c1 += cosf((base * (float)r) / (float)Lk);
        c2 += phib[(size_t)l * Rk + r];
    }
    float c3 = (lane < Bk) ? g_feat[(size_t)lane * Lk + l] : 0.f;
    #pragma unroll
    for (int o = 16; o > 0; o >>= 1) {
        c1 += __shfl_xor_sync(0xffffffffu, c1, o);
        c2 += __shfl_xor_sync(0xffffffffu, c2, o);
        c3 += __shfl_xor_sync(0xffffffffu, c3, o);
    }
    if (lane == 0) {
        int step = *step_p;
        float det_scale = fminf((float)((double)step / 2000.0), 1.0f);
        float scale = det_scale * (c1 / (float)Rk) + (c2 / (float)Rk)
                    + (c3 / (float)Bk) * (g_consts[2] / (float)Rk);
        int gi = l / (Dk / glen);
        float gs = 1.0f / (1.0f + expf(-glog[gi]));
        g_G[l] = gs * scale;
    }
}

// ================= MEGA kernel: fused GEMM1 + GEMM2 =================
// Per CTA (128 rows): phase 1: U(128x256) = Xh@BT1' (K=2048, BK=64) -> smem.
// phase 2: out(128x2048) = U @ WqT' in 16 col-chunks of 128 (K=256 resident).
// 512 threads (16 warps).
// smem layout (bytes):
//   [0, 67584)            U: 128 rows x 264 halves (528 B row)
//   [67584, ...)          phase1 A stages: 2 x 18432 (128 rows x 144 B)
//   [104448, 178176)      phase1 B stages: 2 x 36864 (256 rows x 144 B)
//   phase2 Wq stages: 2 x 67584 at 67584 (reuses phase1 staging area)
#define SMU_BYTES 67584
#define UROWB 528
#define UROWH 264
#define P1_AST 18432
#define P1_BOFF (SMU_BYTES + 2 * P1_AST)
#define P1_BST 36864
#define P2_WST 67584
#define MEGA_SMEM 202752
#define NT1 32

__global__ __launch_bounds__(512, 1) void kMega(const float* __restrict__ bq,
                                                float* __restrict__ out) {
    extern __shared__ char smm[];
    uint32_t sBase = smem_u32(smm);
    int t = threadIdx.x, w = t >> 5, lane = t & 31, g = lane >> 2, tg = lane & 3;
    int rowBase = blockIdx.x * 128;

    // ================== PHASE 1 ==================
    {
        int m0w = (w >> 3) * 64, n0w = (w & 7) * 32;
        uint32_t aOff = (uint32_t)((m0w + (lane & 15)) * 144 + (lane >> 4) * 16);
        uint32_t bOff = (uint32_t)((n0w + (lane & 7) + ((lane >> 4) << 3)) * 144
                                   + ((lane >> 3) & 1) * 16);

        int ar = t >> 2, ah = t & 3;    // A staging: row 0..127, 16-half chunk 0..3
        int br = t >> 1, bh = t & 1;    // B staging: row 0..255, 32-half chunk 0..1
        const __half* Asrc = g_Xh + (size_t)(rowBase + ar) * Dk + ah * 16;
        const __half* Bsrc = g_BT1 + (size_t)br * Dk + bh * 32;

        #define P1_ISSUE(st, tt) do { \
            __half* A = (__half*)(smm + SMU_BYTES + (st) * P1_AST); \
            __half* B = (__half*)(smm + P1_BOFF + (st) * P1_BST); \
            const __half* as = Asrc + (tt) * 64; \
            cp16(A + ar * 72 + ah * 16,     as); \
            cp16(A + ar * 72 + ah * 16 + 8, as + 8); \
            const __half* bs = Bsrc + (tt) * 64; \
            cp16(B + br * 72 + bh * 32,      bs); \
            cp16(B + br * 72 + bh * 32 + 8,  bs + 8); \
            cp16(B + br * 72 + bh * 32 + 16, bs + 16); \
            cp16(B + br * 72 + bh * 32 + 24, bs + 24); \
            CP_COMMIT(); \
        } while (0)

        float acc[4][4][4] = {};

        P1_ISSUE(0, 0);
        CP_WAIT0();
        __syncthreads();

        #pragma unroll 1
        for (int tt = 0; tt < NT1; ++tt) {
            int buf = tt & 1;
            if (tt + 1 < NT1) P1_ISSUE(buf ^ 1, tt + 1);
            uint32_t sA = sBase + SMU_BYTES + buf * P1_AST;
            uint32_t sB = sBase + P1_BOFF + buf * P1_BST;
            #pragma unroll
            for (int ks = 0; ks < 4; ++ks) {
                uint32_t af[4][4], bf[4][2];
                #pragma unroll
                for (int mi = 0; mi < 4; ++mi)
                    LDSM4(af[mi][0], af[mi][1], af[mi][2], af[mi][3],
                          sA + aOff + mi * 16 * 144 + ks * 32);
                #pragma unroll
                for (int ni2 = 0; ni2 < 2; ++ni2) {
                    uint32_t r0, r1, r2, r3;
                    LDSM4(r0, r1, r2, r3, sB + bOff + ni2 * 16 * 144 + ks * 32);
                    bf[ni2 * 2][0] = r0; bf[ni2 * 2][1] = r1;
                    bf[ni2 * 2 + 1][0] = r2; bf[ni2 * 2 + 1][1] = r3;
                }
                #pragma unroll
                for (int mi = 0; mi < 4; ++mi)
                    #pragma unroll
                    for (int ni = 0; ni < 4; ++ni)
                        MMAF16(acc[mi][ni], af[mi], bf[ni]);
            }
            CP_WAIT0();
            __syncthreads();
        }

        // epilogue: U = acc*rstd + nmr*cA + cB -> smem U (fp16)
        __half* Usm = (__half*)smm;
        #pragma unroll
        for (int mi = 0; mi < 4; ++mi) {
            int r1 = m0w + mi * 16 + g;
            float rs1 = g_rstd[rowBase + r1], nm1 = g_nmr[rowBase + r1];
            float rs2 = g_rstd[rowBase + r1 + 8], nm2 = g_nmr[rowBase + r1 + 8];
            #pragma unroll
            for (int ni = 0; ni < 4; ++ni) {
                int cg = n0w + ni * 8 + 2 * tg;
                float ca0 = g_cA[cg], ca1 = g_cA[cg + 1];
                float cb0 = g_cB[cg], cb1 = g_cB[cg + 1];
                *(uint32_t*)(Usm + r1 * UROWH + cg) =
                    h2pack(acc[mi][ni][0] * rs1 + nm1 * ca0 + cb0,
                           acc[mi][ni][1] * rs1 + nm1 * ca1 + cb1);
                *(uint32_t*)(Usm + (r1 + 8) * UROWH + cg) =
                    h2pack(acc[mi][ni][2] * rs2 + nm2 * ca0 + cb0,
                           acc[mi][ni][3] * rs2 + nm2 * ca1 + cb1);
            }
        }
        __syncthreads();
    }

    // ================== PHASE 2 ==================
    {
        int m0 = (w >> 2) * 32, n0 = (w & 3) * 32;
        uint32_t aOff2 = (uint32_t)((m0 + (lane & 15)) * UROWB + (lane >> 4) * 16);
        uint32_t bOff2 = (uint32_t)((n0 + (lane & 7) + ((lane >> 4) << 3)) * UROWB
                                    + ((lane >> 3) & 1) * 16);

        int wr = t >> 2, wq = t & 3;   // Wq staging: row 0..127, 64-half chunk 0..3
        const __half* Wbase = g_WqT + (size_t)wr * Rk + wq * 64;

        #define P2_ISSUE(st, c) do { \
            __half* Wst = (__half*)(smm + SMU_BYTES + (st) * P2_WST); \
            const __half* ws = Wbase + (size_t)(c) * 128 * Rk; \
            __half* wd = Wst + wr * UROWH + wq * 64; \
            cp16(wd,      ws); \
            cp16(wd + 8,  ws + 8); \
            cp16(wd + 16, ws + 16); \
            cp16(wd + 24, ws + 24); \
            cp16(wd + 32, ws + 32); \
            cp16(wd + 40, ws + 40); \
            cp16(wd + 48, ws + 48); \
            cp16(wd + 56, ws + 56); \
            CP_COMMIT(); \
        } while (0)

        P2_ISSUE(0, 0);
        CP_WAIT0();
        __syncthreads();

        #pragma unroll 1
        for (int c = 0; c < 16; ++c) {
            int buf = c & 1;
            if (c + 1 < 16) P2_ISSUE(buf ^ 1, c + 1);
            uint32_t sU = sBase;
            uint32_t sW = sBase + SMU_BYTES + buf * P2_WST;
            float acc2[2][4][4] = {};
            #pragma unroll
            for (int ks = 0; ks < 16; ++ks) {
                uint32_t af[2][4], bf[4][2];
                #pragma unroll
                for (int mi = 0; mi < 2; ++mi)
                    LDSM4(af[mi][0], af[mi][1], af[mi][2], af[mi][3],
                          sU + aOff2 + mi * 16 * UROWB + ks * 32);
                #pragma unroll
                for (int ni2 = 0; ni2 < 2; ++ni2) {
                    uint32_t r0, r1, r2, r3;
                    LDSM4(r0, r1, r2, r3, sW + bOff2 + ni2 * 16 * UROWB + ks * 32);
                    bf[ni2 * 2][0] = r0; bf[ni2 * 2][1] = r1;
                    bf[ni2 * 2 + 1][0] = r2; bf[ni2 * 2 + 1][1] = r3;
                }
                #pragma unroll
                for (int mi = 0; mi < 2; ++mi)
                    #pragma unroll
                    for (int ni = 0; ni < 4; ++ni)
                        MMAF16(acc2[mi][ni], af[mi], bf[ni]);
            }
            // epilogue chunk c
            #pragma unroll
            for (int ni = 0; ni < 4; ++ni) {
                int cg = c * 128 + n0 + ni * 8 + 2 * tg;
                float G0 = g_G[cg], G1 = g_G[cg + 1];
                float q0 = bq[cg], q1 = bq[cg + 1];
                #pragma unroll
                for (int mi = 0; mi < 2; ++mi) {
                    int r1 = rowBase + m0 + mi * 16 + g;
                    float2 o1, o2;
                    o1.x = G0 * (acc2[mi][ni][0] + q0);
                    o1.y = G1 * (acc2[mi][ni][1] + q1);
                    o2.x = G0 * (acc2[mi][ni][2] + q0);
                    o2.y = G1 * (acc2[mi][ni][3] + q1);
                    *(float2*)&out[(size_t)r1 * Dk + cg] = o1;
                    *(float2*)&out[(size_t)(r1 + 8) * Dk + cg] = o2;
                }
            }
            CP_WAIT0();
            __syncthreads();
        }
    }
}

// ---------------- launch ----------------
extern "C" void kernel_launch(void* const* d_in, const int* in_sizes, int n_in,
                              void* d_out, int out_size) {
    const float* x     = (const float*)d_in[0];
    const float* gamma = (const float*)d_in[1];
    const float* beta  = (const float*)d_in[2];
    const float* P     = (const float*)d_in[3];
    const float* dlt   = (const float*)d_in[4];
    const float* phiw  = (const float*)d_in[5];
    const float* phib  = (const float*)d_in[6];
    const float* toep  = (const float*)d_in[7];
    const float* Wq    = (const float*)d_in[8];
    const float* bq    = (const float*)d_in[9];
    const float* glog  = (const float*)d_in[10];
    const int*   step  = (const int*)d_in[11];
    int Kc   = in_sizes[7];
    int glen = in_sizes[10];

    cudaFuncSetAttribute(kMega, cudaFuncAttributeMaxDynamicSharedMemorySize, MEGA_SMEM);

    kPre1<<<801, 256>>>(gamma, beta, phiw, P, toep, Wq, Kc);
    kEg<<<17, 256>>>(dlt);
    kStats<<<2048, 256>>>(x, gamma);
    kApCab<<<384, 256>>>(P, gamma);
    kScale<<<256, 256>>>(phib, glog, step, glen);
    kMega<<<128, 512, MEGA_SMEM>>>(bq, (float*)d_out);
}

// round 8
// speedup vs baseline: 1.0696x; 1.0696x over previous
#include <cuda_runtime.h>
#include <cuda_fp16.h>
#include <cstdint>
#include <math.h>

#define Bk 8
#define Lk 2048
#define Dk 2048
#define Rk 256
#define BLk (Bk * Lk)   // 16384 rows

// ---------------- device scratch ----------------
static __device__ float g_C[Rk * Rk];                 // Toeplitz matrix C[s,i]
static __device__ float g_E[Rk * Rk];                 // E = C @ dlt       (256x256)
static __device__ __half g_BT1[Rk * Dk];              // A'^T fp16         (256x2048)
static __device__ __half g_WqT[Dk * Rk];              // Wq^T fp16         (2048x256)
static __device__ __half g_Xh[(size_t)BLk * Dk];      // X in fp16 (64MB)
static __device__ __half g_U[(size_t)BLk * Rk];       // z_mixed fp16
static __device__ float g_rstd[BLk], g_nmr[BLk];
static __device__ float g_feat[BLk];
static __device__ float g_pg[Rk], g_pb[Rk];
static __device__ float g_cA[Rk], g_cB[Rk];
static __device__ float g_G[Dk];
static __device__ float g_consts[4];
static __device__ float g_pgp[32 * Rk], g_pbp[32 * Rk];

// ---------------- helpers ----------------
__device__ __forceinline__ uint32_t smem_u32(const void* p) {
    uint32_t a;
    asm("{ .reg .u64 t; cvta.to.shared.u64 t, %1; cvt.u32.u64 %0, t; }" : "=r"(a) : "l"(p));
    return a;
}
__device__ __forceinline__ void cp16(void* dst, const void* src) {
    uint32_t d = smem_u32(dst);
    asm volatile("cp.async.cg.shared.global [%0], [%1], 16;" :: "r"(d), "l"(src) : "memory");
}
#define CP_COMMIT() asm volatile("cp.async.commit_group;" ::: "memory")
#define CP_WAIT0()  asm volatile("cp.async.wait_group 0;" ::: "memory")
#define CP_WAIT1()  asm volatile("cp.async.wait_group 1;" ::: "memory")

#define LDSM4(r0, r1, r2, r3, addr) \
    asm volatile("ldmatrix.sync.aligned.m8n8.x4.shared.b16 {%0,%1,%2,%3}, [%4];" \
        : "=r"(r0), "=r"(r1), "=r"(r2), "=r"(r3) : "r"(addr))

#define MMAF16(c, a, b) \
    asm volatile( \
        "mma.sync.aligned.m16n8k16.row.col.f32.f16.f16.f32 " \
        "{%0,%1,%2,%3},{%4,%5,%6,%7},{%8,%9},{%0,%1,%2,%3};" \
        : "+f"((c)[0]), "+f"((c)[1]), "+f"((c)[2]), "+f"((c)[3]) \
        : "r"((a)[0]), "r"((a)[1]), "r"((a)[2]), "r"((a)[3]), \
          "r"((b)[0]), "r"((b)[1]))

__device__ __forceinline__ uint32_t h2pack(float a, float b) {
    __half2 h = __floats2half2_rn(a, b);
    return *reinterpret_cast<uint32_t*>(&h);
}

__device__ __forceinline__ float blockReduce256(float v, float* sm) {
    int t = threadIdx.x;
    sm[t] = v;
    __syncthreads();
    #pragma unroll
    for (int off = 128; off > 0; off >>= 1) {
        if (t < off) sm[t] += sm[t + off];
        __syncthreads();
    }
    float r = sm[0];
    __syncthreads();
    return r;
}

// pad-40-halves row layout (80 bytes): ldmatrix phases conflict-free.
#define PADH 40
#define PADB 80

// ================= fused precompute 1 =================
__global__ __launch_bounds__(256) void kPre1(const float* __restrict__ gamma,
                                             const float* __restrict__ beta,
                                             const float* __restrict__ phiw,
                                             const float* __restrict__ P,
                                             const float* __restrict__ toep,
                                             const float* __restrict__ Wq, int Kc) {
    int bid = blockIdx.x, t = threadIdx.x;
    if (bid == 0) {
        __shared__ float sm[256];
        float a = 0.f, b = 0.f, c = 0.f;
        for (int j = t; j < Dk; j += 256) { a += gamma[j]; b += beta[j]; }
        for (int j = t; j < Rk; j += 256) { c += phiw[j]; }
        float A = blockReduce256(a, sm);
        float B = blockReduce256(b, sm);
        float C = blockReduce256(c, sm);
        if (t == 0) { g_consts[0] = A; g_consts[1] = B; g_consts[2] = C; }
    } else if (bid <= 32) {
        int chunk = bid - 1;
        float ag = 0.f, ab = 0.f;
        #pragma unroll 4
        for (int j = 0; j < 64; j++) {
            int d = chunk * 64 + j;
            float p = P[(size_t)d * Rk + t];
            ag += gamma[d] * p;
            ab += beta[d] * p;
        }
        g_pgp[chunk * Rk + t] = ag;
        g_pbp[chunk * Rk + t] = ab;
    } else if (bid <= 288) {
        int s = bid - 33;
        int pad = (Kc - 1) >> 1;
        int idx = t - s + pad;
        g_C[s * Rk + t] = (idx >= 0 && idx < Kc) ? toep[idx] : 0.f;
    } else {
        int id = bid - 289;
        int bx = id & 63, by = id >> 6;
        __shared__ float tile[32][33];
        int tx = t & 31, ty8 = t >> 5;
        #pragma unroll
        for (int i = 0; i < 32; i += 8)
            tile[ty8 + i][tx] = Wq[(size_t)(by * 32 + ty8 + i) * Dk + bx * 32 + tx];
        __syncthreads();
        #pragma unroll
        for (int i = 0; i < 32; i += 8)
            g_WqT[(size_t)(bx * 32 + ty8 + i) * Rk + by * 32 + tx] =
                __float2half_rn(tile[tx][ty8 + i]);
    }
}

// ================= kEg: E = C @ dlt + pgb2 reduce =================
__global__ __launch_bounds__(256) void kEg(const float* __restrict__ dlt) {
    int bid = blockIdx.x, t = threadIdx.x;
    if (bid == 16) {
        float a = 0.f, b = 0.f;
        #pragma unroll
        for (int c = 0; c < 32; c++) { a += g_pgp[c * Rk + t]; b += g_pbp[c * Rk + t]; }
        g_pg[t] = a;
        g_pb[t] = b;
        return;
    }
    __shared__ float Cs[16][66];
    __shared__ float Ds[16][68];
    int bx = bid & 3, by = bid >> 2;
    int sBase = by * 64, rBase = bx * 64;
    int ty = t >> 4, tx = t & 15;
    float acc[4][4] = {};
    for (int k0 = 0; k0 < Rk; k0 += 16) {
        {
            int m = t >> 2, kq = (t & 3) * 4;
            float4 v = *(const float4*)&g_C[(size_t)(sBase + m) * Rk + k0 + kq];
            Cs[kq + 0][m] = v.x; Cs[kq + 1][m] = v.y; Cs[kq + 2][m] = v.z; Cs[kq + 3][m] = v.w;
        }
        {
            int kk = t >> 4, n4 = (t & 15) * 4;
            float4 v = *(const float4*)&dlt[(size_t)(k0 + kk) * Rk + rBase + n4];
            *(float4*)&Ds[kk][n4] = v;
        }
        __syncthreads();
        #pragma unroll
        for (int k = 0; k < 16; k++) {
            float a[4], b[4];
            #pragma unroll
            for (int i = 0; i < 4; i++) a[i] = Cs[k][ty * 4 + i];
            #pragma unroll
            for (int j = 0; j < 4; j++) b[j] = Ds[k][tx * 4 + j];
            #pragma unroll
            for (int i = 0; i < 4; i++)
                #pragma unroll
                for (int j = 0; j < 4; j++) acc[i][j] += a[i] * b[j];
        }
        __syncthreads();
    }
    #pragma unroll
    for (int i = 0; i < 4; i++)
        #pragma unroll
        for (int j = 0; j < 4; j++)
            g_E[(size_t)(sBase + ty * 4 + i) * Rk + rBase + tx * 4 + j] = acc[i][j];
}

// ================= kAp: A'^T = gamma ⊙ (P@E^T) -> fp16, 512 threads =================
__global__ __launch_bounds__(512) void kAp(const float* __restrict__ P,
                                           const float* __restrict__ gamma) {
    __shared__ float Ps[16][64];
    __shared__ float Es[16][68];
    int bid = blockIdx.x, t = threadIdx.x;
    int bx = bid & 3, by = bid >> 2;
    int dBase = by * 64, sBase = bx * 64;
    int ty = t >> 4, tx = t & 15;   // ty 0..31 (2 rows each), tx 0..15 (4 cols each)
    float acc[2][4] = {};
    int m = t >> 3, kq = (t & 7) * 2;
    for (int k0 = 0; k0 < Rk; k0 += 16) {
        {
            float2 v = *(const float2*)&P[(size_t)(dBase + m) * Rk + k0 + kq];
            Ps[kq][m] = v.x; Ps[kq + 1][m] = v.y;
        }
        {
            float2 v = *(const float2*)&g_E[(size_t)(sBase + m) * Rk + k0 + kq];
            Es[kq][m] = v.x; Es[kq + 1][m] = v.y;
        }
        __syncthreads();
        #pragma unroll
        for (int k = 0; k < 16; k++) {
            float a0 = Ps[k][ty * 2], a1 = Ps[k][ty * 2 + 1];
            float b[4];
            #pragma unroll
            for (int j = 0; j < 4; j++) b[j] = Es[k][tx * 4 + j];
            #pragma unroll
            for (int j = 0; j < 4; j++) { acc[0][j] += a0 * b[j]; acc[1][j] += a1 * b[j]; }
        }
        __syncthreads();
    }
    #pragma unroll
    for (int i = 0; i < 2; i++) {
        int d = dBase + ty * 2 + i;
        float g = gamma[d];
        #pragma unroll
        for (int j = 0; j < 4; j++) {
            int s = sBase + tx * 4 + j;
            g_BT1[(size_t)s * Dk + d] = __float2half_rn(g * acc[i][j]);
        }
    }
}

// ================= kStats: LN stats + fp16 X + cA/cB =================
// bid < 2048: stats for 8 rows (warp per row). bid >= 2048: cA/cB for s = bid-2048.
__global__ __launch_bounds__(256) void kStats(const float* __restrict__ X,
                                              const float* __restrict__ gamma) {
    int bid = blockIdx.x, t = threadIdx.x;
    if (bid >= 2048) {
        __shared__ float sm[256];
        int s = bid - 2048;
        float e = g_E[(size_t)s * Rk + t];
        float ca = blockReduce256(g_pg[t] * e, sm);
        float cb = blockReduce256(g_pb[t] * e, sm);
        if (t == 0) { g_cA[s] = ca; g_cB[s] = cb; }
        return;
    }
    int w = t >> 5, lane = t & 31;
    int row = bid * 8 + w;
    const float4* Xr = (const float4*)(X + (size_t)row * Dk);
    const float4* Gm = (const float4*)gamma;
    __half* Xo = g_Xh + (size_t)row * Dk;
    float s = 0.f, s2 = 0.f, sg = 0.f;
    #pragma unroll
    for (int j = 0; j < 16; j++) {
        int idx = j * 32 + lane;
        float4 v = Xr[idx];
        float4 gv = Gm[idx];
        s  += (v.x + v.y) + (v.z + v.w);
        s2 += v.x * v.x + v.y * v.y + v.z * v.z + v.w * v.w;
        sg += gv.x * v.x + gv.y * v.y + gv.z * v.z + gv.w * v.w;
        uint2 pk = { h2pack(v.x, v.y), h2pack(v.z, v.w) };
        *(uint2*)(Xo + idx * 4) = pk;
    }
    #pragma unroll
    for (int o = 16; o > 0; o >>= 1) {
        s  += __shfl_xor_sync(0xffffffffu, s, o);
        s2 += __shfl_xor_sync(0xffffffffu, s2, o);
        sg += __shfl_xor_sync(0xffffffffu, sg, o);
    }
    if (lane == 0) {
        float C0 = g_consts[0], C1 = g_consts[1];
        float mean = s * (1.f / Dk);
        float var = s2 * (1.f / Dk) - mean * mean;
        float rstd = rsqrtf(var + 1e-5f);
        g_rstd[row] = rstd;
        g_nmr[row] = -mean * rstd;
        g_feat[row] = (sg - mean * C0) * rstd * (1.f / Dk) + C1 * (1.f / Dk);
    }
}

// G[l] = sigmoid(g_logit[..]) * scale[l]
__global__ void kScale(const float* __restrict__ phib, const float* __restrict__ glog,
                       const int* __restrict__ step_p, int glen) {
    int w = threadIdx.x >> 5, lane = threadIdx.x & 31;
    int l = blockIdx.x * 8 + w;
    const float PI_F = 3.14159274101257324f;
    float base = PI_F * ((float)l + 0.5f);
    float c1 = 0.f, c2 = 0.f;
    #pragma unroll
    for (int j = 0; j < 8; j++) {
        int r = lane + 32 * j;
        c1 += cosf((base * (float)r) / (float)Lk);
        c2 += phib[(size_t)l * Rk + r];
    }
    float c3 = (lane < Bk) ? g_feat[(size_t)lane * Lk + l] : 0.f;
    #pragma unroll
    for (int o = 16; o > 0; o >>= 1) {
        c1 += __shfl_xor_sync(0xffffffffu, c1, o);
        c2 += __shfl_xor_sync(0xffffffffu, c2, o);
        c3 += __shfl_xor_sync(0xffffffffu, c3, o);
    }
    if (lane == 0) {
        int step = *step_p;
        float det_scale = fminf((float)((double)step / 2000.0), 1.0f);
        float scale = det_scale * (c1 / (float)Rk) + (c2 / (float)Rk)
                    + (c3 / (float)Bk) * (g_consts[2] / (float)Rk);
        int gi = l / (Dk / glen);
        float gs = 1.0f / (1.0f + expf(-glog[gi]));
        g_G[l] = gs * scale;
    }
}

// ================= shared GEMM config: tile 128x256 (rows x cols/N), BK=32 ======
// 512 threads, 16 warps, warp tile 64x32. 3-stage cp.async.
// Stage: A 128x40h (10240 B) + B 256x40h (20480 B) = 30720 B. Total 92160 B.
#define GST   30720
#define GSMEM 92160

// ================= GEMM 1: U = (Xh@BT1')*rstd + nmr*cA + cB =================
#define NT1 64
__global__ __launch_bounds__(512, 1) void kGemm1MMA() {
    extern __shared__ char smm[];
    uint32_t sBase = smem_u32(smm);
    int t = threadIdx.x, w = t >> 5, lane = t & 31, g = lane >> 2, tg = lane & 3;
    int rowBase = blockIdx.x * 128;
    int m0w = (w >> 3) * 64, n0w = (w & 7) * 32;

    uint32_t aOff = (uint32_t)((m0w + (lane & 15)) * PADB + (lane >> 4) * 16);
    uint32_t bOff = 10240u + (uint32_t)((n0w + (lane & 7) + ((lane >> 4) << 3)) * PADB
                                        + ((lane >> 3) & 1) * 16);

    int ar = t >> 2, ac = t & 3;    // A: 128 rows x 4 chunks of 8 halves
    int br = t >> 1, bc = t & 1;    // B: 256 rows x 2 chunks of 16 halves
    const __half* Asrc = g_Xh + (size_t)(rowBase + ar) * Dk + ac * 8;
    const __half* Bsrc = g_BT1 + (size_t)br * Dk + bc * 16;

    #define G1_ISSUE(st, tt) do { \
        char* S = smm + (st) * GST; \
        cp16((__half*)S + ar * PADH + ac * 8, Asrc + (size_t)(tt) * 32); \
        __half* B = (__half*)(S + 10240); \
        const __half* bs = Bsrc + (size_t)(tt) * 32; \
        cp16(B + br * PADH + bc * 16,     bs); \
        cp16(B + br * PADH + bc * 16 + 8, bs + 8); \
        CP_COMMIT(); \
    } while (0)

    float acc[4][4][4] = {};

    G1_ISSUE(0, 0);
    G1_ISSUE(1, 1);
    CP_WAIT1();
    __syncthreads();

    #pragma unroll 1
    for (int tt = 0; tt < NT1; ++tt) {
        if (tt + 2 < NT1) G1_ISSUE((tt + 2) % 3, tt + 2);
        uint32_t sb = sBase + (tt % 3) * GST;
        #pragma unroll
        for (int ks = 0; ks < 2; ++ks) {
            uint32_t af[4][4], bf[4][2];
            #pragma unroll
            for (int mi = 0; mi < 4; ++mi)
                LDSM4(af[mi][0], af[mi][1], af[mi][2], af[mi][3],
                      sb + aOff + mi * 16 * PADB + ks * 32);
            #pragma unroll
            for (int ni2 = 0; ni2 < 2; ++ni2) {
                uint32_t r0, r1, r2, r3;
                LDSM4(r0, r1, r2, r3, sb + bOff + ni2 * 16 * PADB + ks * 32);
                bf[ni2 * 2][0] = r0; bf[ni2 * 2][1] = r1;
                bf[ni2 * 2 + 1][0] = r2; bf[ni2 * 2 + 1][1] = r3;
            }
            #pragma unroll
            for (int mi = 0; mi < 4; ++mi)
                #pragma unroll
                for (int ni = 0; ni < 4; ++ni)
                    MMAF16(acc[mi][ni], af[mi], bf[ni]);
        }
        if (tt + 2 < NT1) { CP_WAIT1(); }
        else if (tt + 1 < NT1) { CP_WAIT0(); }
        __syncthreads();
    }

    // epilogue -> g_U (fp16)
    #pragma unroll
    for (int mi = 0; mi < 4; ++mi) {
        int r1 = m0w + mi * 16 + g;
        float rs1 = g_rstd[rowBase + r1], nm1 = g_nmr[rowBase + r1];
        float rs2 = g_rstd[rowBase + r1 + 8], nm2 = g_nmr[rowBase + r1 + 8];
        #pragma unroll
        for (int ni = 0; ni < 4; ++ni) {
            int cg = n0w + ni * 8 + 2 * tg;
            float ca0 = g_cA[cg], ca1 = g_cA[cg + 1];
            float cb0 = g_cB[cg], cb1 = g_cB[cg + 1];
            *(uint32_t*)(g_U + (size_t)(rowBase + r1) * Rk + cg) =
                h2pack(acc[mi][ni][0] * rs1 + nm1 * ca0 + cb0,
                       acc[mi][ni][1] * rs1 + nm1 * ca1 + cb1);
            *(uint32_t*)(g_U + (size_t)(rowBase + r1 + 8) * Rk + cg) =
                h2pack(acc[mi][ni][2] * rs2 + nm2 * ca0 + cb0,
                       acc[mi][ni][3] * rs2 + nm2 * ca1 + cb1);
        }
    }
}

// ================= GEMM 2: out = G[d]*(U @ Wq + bq) =================
// grid (8, 128): col tiles of 256, row tiles of 128. K=256, NT=8.
#define NT2 8
__global__ __launch_bounds__(512, 1) void kGemm2MMA(const float* __restrict__ bq,
                                                    float* __restrict__ out) {
    extern __shared__ char smm[];
    uint32_t sBase = smem_u32(smm);
    int t = threadIdx.x, w = t >> 5, lane = t & 31, g = lane >> 2, tg = lane & 3;
    int rowBase = blockIdx.y * 128, colBase = blockIdx.x * 256;
    int m0w = (w >> 3) * 64, n0w = (w & 7) * 32;

    uint32_t aOff = (uint32_t)((m0w + (lane & 15)) * PADB + (lane >> 4) * 16);
    uint32_t bOff = 10240u + (uint32_t)((n0w + (lane & 7) + ((lane >> 4) << 3)) * PADB
                                        + ((lane >> 3) & 1) * 16);

    int ar = t >> 2, ac = t & 3;
    int br = t >> 1, bc = t & 1;
    const __half* Asrc = g_U + (size_t)(rowBase + ar) * Rk + ac * 8;
    const __half* Bsrc = g_WqT + (size_t)(colBase + br) * Rk + bc * 16;

    #define G2_ISSUE(st, tt) do { \
        char* S = smm + (st) * GST; \
        cp16((__half*)S + ar * PADH + ac * 8, Asrc + (size_t)(tt) * 32); \
        __half* B = (__half*)(S + 10240); \
        const __half* bs = Bsrc + (size_t)(tt) * 32; \
        cp16(B + br * PADH + bc * 16,     bs); \
        cp16(B + br * PADH + bc * 16 + 8, bs + 8); \
        CP_COMMIT(); \
    } while (0)

    float acc[4][4][4] = {};

    G2_ISSUE(0, 0);
    G2_ISSUE(1, 1);
    CP_WAIT1();
    __syncthreads();

    #pragma unroll 1
    for (int tt = 0; tt < NT2; ++tt) {
        if (tt + 2 < NT2) G2_ISSUE((tt + 2) % 3, tt + 2);
        uint32_t sb = sBase + (tt % 3) * GST;
        #pragma unroll
        for (int ks = 0; ks < 2; ++ks) {
            uint32_t af[4][4], bf[4][2];
            #pragma unroll
            for (int mi = 0; mi < 4; ++mi)
                LDSM4(af[mi][0], af[mi][1], af[mi][2], af[mi][3],
                      sb + aOff + mi * 16 * PADB + ks * 32);
            #pragma unroll
            for (int ni2 = 0; ni2 < 2; ++ni2) {
                uint32_t r0, r1, r2, r3;
                LDSM4(r0, r1, r2, r3, sb + bOff + ni2 * 16 * PADB + ks * 32);
                bf[ni2 * 2][0] = r0; bf[ni2 * 2][1] = r1;
                bf[ni2 * 2 + 1][0] = r2; bf[ni2 * 2 + 1][1] = r3;
            }
            #pragma unroll
            for (int mi = 0; mi < 4; ++mi)
                #pragma unroll
                for (int ni = 0; ni < 4; ++ni)
                    MMAF16(acc[mi][ni], af[mi], bf[ni]);
        }
        if (tt + 2 < NT2) { CP_WAIT1(); }
        else if (tt + 1 < NT2) { CP_WAIT0(); }
        __syncthreads();
    }

    #pragma unroll
    for (int ni = 0; ni < 4; ++ni) {
        int cg = colBase + n0w + ni * 8 + 2 * tg;
        float G0 = g_G[cg], G1 = g_G[cg + 1];
        float q0 = bq[cg], q1 = bq[cg + 1];
        #pragma unroll
        for (int mi = 0; mi < 4; ++mi) {
            int r1 = rowBase + m0w + mi * 16 + g;
            float2 o1, o2;
            o1.x = G0 * (acc[mi][ni][0] + q0);
            o1.y = G1 * (acc[mi][ni][1] + q1);
            o2.x = G0 * (acc[mi][ni][2] + q0);
            o2.y = G1 * (acc[mi][ni][3] + q1);
            *(float2*)&out[(size_t)r1 * Dk + cg] = o1;
            *(float2*)&out[(size_t)(r1 + 8) * Dk + cg] = o2;
        }
    }
}

// ---------------- launch ----------------
extern "C" void kernel_launch(void* const* d_in, const int* in_sizes, int n_in,
                              void* d_out, int out_size) {
    const float* x     = (const float*)d_in[0];
    const float* gamma = (const float*)d_in[1];
    const float* beta  = (const float*)d_in[2];
    const float* P     = (const float*)d_in[3];
    const float* dlt   = (const float*)d_in[4];
    const float* phiw  = (const float*)d_in[5];
    const float* phib  = (const float*)d_in[6];
    const float* toep  = (const float*)d_in[7];
    const float* Wq    = (const float*)d_in[8];
    const float* bq    = (const float*)d_in[9];
    const float* glog  = (const float*)d_in[10];
    const int*   step  = (const int*)d_in[11];
    int Kc   = in_sizes[7];
    int glen = in_sizes[10];

    cudaFuncSetAttribute(kGemm1MMA, cudaFuncAttributeMaxDynamicSharedMemorySize, GSMEM);
    cudaFuncSetAttribute(kGemm2MMA, cudaFuncAttributeMaxDynamicSharedMemorySize, GSMEM);

    kPre1<<<801, 256>>>(gamma, beta, phiw, P, toep, Wq, Kc);
    kEg<<<17, 256>>>(dlt);
    kAp<<<128, 512>>>(P, gamma);
    kStats<<<2304, 256>>>(x, gamma);
    kScale<<<256, 256>>>(phib, glog, step, glen);
    kGemm1MMA<<<128, 512, GSMEM>>>();
    kGemm2MMA<<<dim3(8, 128), 512, GSMEM>>>(bq, (float*)d_out);
}

// round 10
// speedup vs baseline: 1.0939x; 1.0227x over previous
#include <cuda_runtime.h>
#include <cuda_fp16.h>
#include <cstdint>
#include <math.h>

#define Bk 8
#define Lk 2048
#define Dk 2048
#define Rk 256
#define BLk (Bk * Lk)   // 16384 rows

// ---------------- device scratch ----------------
static __device__ float g_C[Rk * Rk];                 // Toeplitz matrix C[s,i]
static __device__ float g_E[Rk * Rk];                 // E = C @ dlt       (256x256)
static __device__ float g_ApP[2][(size_t)Rk * Dk];    // kAp k-split partials
static __device__ __half g_BT1[Rk * Dk];              // A'^T fp16         (256x2048)
static __device__ __half g_WqT[Dk * Rk];              // Wq^T fp16         (2048x256)
static __device__ __half g_U[(size_t)BLk * Rk];       // z_mixed fp16
static __device__ float g_feat[BLk];
static __device__ float g_pg[Rk], g_pb[Rk];
static __device__ float g_cA[Rk], g_cB[Rk];
static __device__ float g_G[Dk];
static __device__ float g_consts[4];
static __device__ float g_pgp[32 * Rk], g_pbp[32 * Rk];

// ---------------- helpers ----------------
__device__ __forceinline__ uint32_t smem_u32(const void* p) {
    uint32_t a;
    asm("{ .reg .u64 t; cvta.to.shared.u64 t, %1; cvt.u32.u64 %0, t; }" : "=r"(a) : "l"(p));
    return a;
}
__device__ __forceinline__ void cp16(void* dst, const void* src) {
    uint32_t d = smem_u32(dst);
    asm volatile("cp.async.cg.shared.global [%0], [%1], 16;" :: "r"(d), "l"(src) : "memory");
}
#define CP_COMMIT() asm volatile("cp.async.commit_group;" ::: "memory")
#define CP_WAIT0()  asm volatile("cp.async.wait_group 0;" ::: "memory")
#define CP_WAIT1()  asm volatile("cp.async.wait_group 1;" ::: "memory")

#define LDSM4(r0, r1, r2, r3, addr) \
    asm volatile("ldmatrix.sync.aligned.m8n8.x4.shared.b16 {%0,%1,%2,%3}, [%4];" \
        : "=r"(r0), "=r"(r1), "=r"(r2), "=r"(r3) : "r"(addr))

#define MMAF16(c, a, b) \
    asm volatile( \
        "mma.sync.aligned.m16n8k16.row.col.f32.f16.f16.f32 " \
        "{%0,%1,%2,%3},{%4,%5,%6,%7},{%8,%9},{%0,%1,%2,%3};" \
        : "+f"((c)[0]), "+f"((c)[1]), "+f"((c)[2]), "+f"((c)[3]) \
        : "r"((a)[0]), "r"((a)[1]), "r"((a)[2]), "r"((a)[3]), \
          "r"((b)[0]), "r"((b)[1]))

__device__ __forceinline__ uint32_t h2pack(float a, float b) {
    __half2 h = __floats2half2_rn(a, b);
    return *reinterpret_cast<uint32_t*>(&h);
}

__device__ __forceinline__ float blockReduce256(float v, float* sm) {
    int t = threadIdx.x;
    sm[t] = v;
    __syncthreads();
    #pragma unroll
    for (int off = 128; off > 0; off >>= 1) {
        if (t < off) sm[t] += sm[t + off];
        __syncthreads();
    }
    float r = sm[0];
    __syncthreads();
    return r;
}

// pad-40-halves row layout (80 bytes): ldmatrix phases conflict-free.
#define PADH 40
#define PADB 80

// ================= fused precompute 1 =================
// bid 0: consts; 1..32: pgb partials; 33..288: build C; 289..800: WqT transpose
__global__ __launch_bounds__(256) void kPre1(const float* __restrict__ gamma,
                                             const float* __restrict__ beta,
                                             const float* __restrict__ phiw,
                                             const float* __restrict__ P,
                                             const float* __restrict__ toep,
                                             const float* __restrict__ Wq, int Kc) {
    int bid = blockIdx.x, t = threadIdx.x;
    if (bid == 0) {
        __shared__ float sm[256];
        float a = 0.f, b = 0.f, c = 0.f;
        for (int j = t; j < Dk; j += 256) { a += gamma[j]; b += beta[j]; }
        for (int j = t; j < Rk; j += 256) { c += phiw[j]; }
        float A = blockReduce256(a, sm);
        float B = blockReduce256(b, sm);
        float C = blockReduce256(c, sm);
        if (t == 0) { g_consts[0] = A; g_consts[1] = B; g_consts[2] = C; }
    } else if (bid <= 32) {
        int chunk = bid - 1;
        float ag = 0.f, ab = 0.f;
        #pragma unroll 4
        for (int j = 0; j < 64; j++) {
            int d = chunk * 64 + j;
            float p = P[(size_t)d * Rk + t];
            ag += gamma[d] * p;
            ab += beta[d] * p;
        }
        g_pgp[chunk * Rk + t] = ag;
        g_pbp[chunk * Rk + t] = ab;
    } else if (bid <= 288) {
        int s = bid - 33;
        int pad = (Kc - 1) >> 1;
        int idx = t - s + pad;
        g_C[s * Rk + t] = (idx >= 0 && idx < Kc) ? toep[idx] : 0.f;
    } else {
        int id = bid - 289;
        int bx = id & 63, by = id >> 6;
        __shared__ float tile[32][33];
        int tx = t & 31, ty8 = t >> 5;
        #pragma unroll
        for (int i = 0; i < 32; i += 8)
            tile[ty8 + i][tx] = Wq[(size_t)(by * 32 + ty8 + i) * Dk + bx * 32 + tx];
        __syncthreads();
        #pragma unroll
        for (int i = 0; i < 32; i += 8)
            g_WqT[(size_t)(bx * 32 + ty8 + i) * Rk + by * 32 + tx] =
                __float2half_rn(tile[tx][ty8 + i]);
    }
}

// ================= kEg: E = C @ dlt + pgb2 reduce =================
__global__ __launch_bounds__(256) void kEg(const float* __restrict__ dlt) {
    int bid = blockIdx.x, t = threadIdx.x;
    if (bid == 16) {
        float a = 0.f, b = 0.f;
        #pragma unroll
        for (int c = 0; c < 32; c++) { a += g_pgp[c * Rk + t]; b += g_pbp[c * Rk + t]; }
        g_pg[t] = a;
        g_pb[t] = b;
        return;
    }
    __shared__ float Cs[16][66];
    __shared__ float Ds[16][68];
    int bx = bid & 3, by = bid >> 2;
    int sBase = by * 64, rBase = bx * 64;
    int ty = t >> 4, tx = t & 15;
    float acc[4][4] = {};
    for (int k0 = 0; k0 < Rk; k0 += 16) {
        {
            int m = t >> 2, kq = (t & 3) * 4;
            float4 v = *(const float4*)&g_C[(size_t)(sBase + m) * Rk + k0 + kq];
            Cs[kq + 0][m] = v.x; Cs[kq + 1][m] = v.y; Cs[kq + 2][m] = v.z; Cs[kq + 3][m] = v.w;
        }
        {
            int kk = t >> 4, n4 = (t & 15) * 4;
            float4 v = *(const float4*)&dlt[(size_t)(k0 + kk) * Rk + rBase + n4];
            *(float4*)&Ds[kk][n4] = v;
        }
        __syncthreads();
        #pragma unroll
        for (int k = 0; k < 16; k++) {
            float a[4], b[4];
            #pragma unroll
            for (int i = 0; i < 4; i++) a[i] = Cs[k][ty * 4 + i];
            #pragma unroll
            for (int j = 0; j < 4; j++) b[j] = Ds[k][tx * 4 + j];
            #pragma unroll
            for (int i = 0; i < 4; i++)
                #pragma unroll
                for (int j = 0; j < 4; j++) acc[i][j] += a[i] * b[j];
        }
        __syncthreads();
    }
    #pragma unroll
    for (int i = 0; i < 4; i++)
        #pragma unroll
        for (int j = 0; j < 4; j++)
            g_E[(size_t)(sBase + ty * 4 + i) * Rk + rBase + tx * 4 + j] = acc[i][j];
}

// ================= kApPart: partial A'^T over half of K =================
__global__ __launch_bounds__(256) void kApPart(const float* __restrict__ P) {
    __shared__ __align__(16) float Ps[16][64];
    __shared__ __align__(16) float Es[16][68];
    int bid = blockIdx.x, t = threadIdx.x;
    int kh = bid >> 7;
    int rem = bid & 127;
    int bx = rem & 3, by = rem >> 2;
    int dBase = by * 64, sBase = bx * 64, kBase = kh * 128;
    int ty = t >> 4, tx = t & 15;
    float acc[4][4] = {};
    for (int c = 0; c < 8; c++) {
        int k0 = kBase + c * 16;
        {
            int m = t >> 2, kq = (t & 3) * 4;
            float4 v = *(const float4*)&P[(size_t)(dBase + m) * Rk + k0 + kq];
            Ps[kq + 0][m] = v.x; Ps[kq + 1][m] = v.y; Ps[kq + 2][m] = v.z; Ps[kq + 3][m] = v.w;
            float4 e = *(const float4*)&g_E[(size_t)(sBase + m) * Rk + k0 + kq];
            Es[kq + 0][m] = e.x; Es[kq + 1][m] = e.y; Es[kq + 2][m] = e.z; Es[kq + 3][m] = e.w;
        }
        __syncthreads();
        #pragma unroll
        for (int k = 0; k < 16; k++) {
            float4 av = *(const float4*)&Ps[k][ty * 4];
            float4 bv = *(const float4*)&Es[k][tx * 4];
            float a[4] = { av.x, av.y, av.z, av.w };
            float b[4] = { bv.x, bv.y, bv.z, bv.w };
            #pragma unroll
            for (int i = 0; i < 4; i++)
                #pragma unroll
                for (int j = 0; j < 4; j++) acc[i][j] += a[i] * b[j];
        }
        __syncthreads();
    }
    #pragma unroll
    for (int j = 0; j < 4; j++) {
        int s = sBase + tx * 4 + j;
        float4 o = { acc[0][j], acc[1][j], acc[2][j], acc[3][j] };
        *(float4*)&g_ApP[kh][(size_t)s * Dk + dBase + ty * 4] = o;
    }
}

// ================= kComb: BT1 = fp16(gamma*(p0+p1)); cA/cB =================
__global__ __launch_bounds__(256) void kComb(const float* __restrict__ gamma) {
    int bid = blockIdx.x, t = threadIdx.x;
    if (bid >= 256) {
        __shared__ float sm[256];
        int s = bid - 256;
        float e = g_E[(size_t)s * Rk + t];
        float ca = blockReduce256(g_pg[t] * e, sm);
        float cb = blockReduce256(g_pb[t] * e, sm);
        if (t == 0) { g_cA[s] = ca; g_cB[s] = cb; }
        return;
    }
    int s = bid;
    #pragma unroll
    for (int it = 0; it < 2; it++) {
        int d0 = it * 1024 + t * 4;
        float4 p0 = *(const float4*)&g_ApP[0][(size_t)s * Dk + d0];
        float4 p1 = *(const float4*)&g_ApP[1][(size_t)s * Dk + d0];
        float4 gv = *(const float4*)&gamma[d0];
        uint2 pk;
        pk.x = h2pack(gv.x * (p0.x + p1.x), gv.y * (p0.y + p1.y));
        pk.y = h2pack(gv.z * (p0.z + p1.z), gv.w * (p0.w + p1.w));
        *(uint2*)&g_BT1[(size_t)s * Dk + d0] = pk;
    }
}

// G[l] = sigmoid(g_logit[..]) * scale[l]  (needs g_feat from GEMM1)
__global__ void kScale(const float* __restrict__ phib, const float* __restrict__ glog,
                       const int* __restrict__ step_p, int glen) {
    int w = threadIdx.x >> 5, lane = threadIdx.x & 31;
    int l = blockIdx.x * 8 + w;
    const float PI_F = 3.14159274101257324f;
    float base = PI_F * ((float)l + 0.5f);
    float c1 = 0.f, c2 = 0.f;
    #pragma unroll
    for (int j = 0; j < 8; j++) {
        int r = lane + 32 * j;
        c1 += cosf((base * (float)r) / (float)Lk);
        c2 += phib[(size_t)l * Rk + r];
    }
    float c3 = (lane < Bk) ? g_feat[(size_t)lane * Lk + l] : 0.f;
    #pragma unroll
    for (int o = 16; o > 0; o >>= 1) {
        c1 += __shfl_xor_sync(0xffffffffu, c1, o);
        c2 += __shfl_xor_sync(0xffffffffu, c2, o);
        c3 += __shfl_xor_sync(0xffffffffu, c3, o);
    }
    if (lane == 0) {
        int step = *step_p;
        float det_scale = fminf((float)((double)step / 2000.0), 1.0f);
        float scale = det_scale * (c1 / (float)Rk) + (c2 / (float)Rk)
                    + (c3 / (float)Bk) * (g_consts[2] / (float)Rk);
        int gi = l / (Dk / glen);
        float gs = 1.0f / (1.0f + expf(-glog[gi]));
        g_G[l] = gs * scale;
    }
}

// ================= fp16 mma GEMM 1 — TRUE R5 version (94.2us measured) ==========
// U = (X @ A')*rstd + nmr*cA + cB; M=16384, N=256, K=2048. BK=32, NT=64,
// grid 128 (X read once), 512 thr. Warps 0-7 stage A (2 thr/row, 16 floats each,
// fp32->fp16 + LN stats), warps 8-15 stage B (cp.async). All compute 64x32 tiles.
#define NT1 64
#define SM1_AS0   0
#define SM1_AS1   10240
#define SM1_BS0   20480
#define SM1_BS1   40960
#define SM1_GAM   61440
#define SM1_RSTD  69632
#define SM1_NMR   70144
#define SM1_TOTAL 70656

__global__ __launch_bounds__(512) void kGemm1MMA(const float* __restrict__ X,
                                                 const float* __restrict__ gamma) {
    extern __shared__ char sm1[];
    __half* As[2] = { (__half*)(sm1 + SM1_AS0), (__half*)(sm1 + SM1_AS1) };
    __half* Bs[2] = { (__half*)(sm1 + SM1_BS0), (__half*)(sm1 + SM1_BS1) };
    float* s_gam  = (float*)(sm1 + SM1_GAM);
    float* s_rstd = (float*)(sm1 + SM1_RSTD);
    float* s_nmr  = (float*)(sm1 + SM1_NMR);

    int t = threadIdx.x, w = t >> 5, lane = t & 31, g = lane >> 2, tg = lane & 3;
    int rowBase = blockIdx.x * 128;
    int m0w = (w >> 3) * 64, n0w = (w & 7) * 32;

    for (int i = t; i < Dk / 4; i += 512)
        ((float4*)s_gam)[i] = ((const float4*)gamma)[i];

    uint32_t sA[2] = { smem_u32(As[0]), smem_u32(As[1]) };
    uint32_t sB[2] = { smem_u32(Bs[0]), smem_u32(Bs[1]) };
    uint32_t aBase = (uint32_t)((m0w + (lane & 15)) * PADB + (lane >> 4) * 16);
    uint32_t bBase = (uint32_t)((n0w + (lane & 7) + ((lane >> 4) << 3)) * PADB
                                + ((lane >> 3) & 1) * 16);

    int lr = t >> 1, h = t & 1;   // A stagers: row (0..127), 16-float half
    int t2 = t & 255;             // B stagers row
    const float4* Xr = (const float4*)(X + (size_t)(rowBase + lr) * Dk);
    const __half* Bsrc = g_BT1 + (size_t)t2 * Dk;

    float acc[4][4][4] = {};
    float s0 = 0.f, s20 = 0.f, sg0 = 0.f;

    __syncthreads();  // gamma visible

    #define G1_APROC(st, tt, q) do { \
        _Pragma("unroll") \
        for (int j = 0; j < 4; j++) { \
            float4 gv = ((const float4*)s_gam)[(tt) * 8 + h * 4 + j]; \
            s0  += (q[j].x + q[j].y) + (q[j].z + q[j].w); \
            s20 += q[j].x*q[j].x + q[j].y*q[j].y + q[j].z*q[j].z + q[j].w*q[j].w; \
            sg0 += gv.x*q[j].x + gv.y*q[j].y + gv.z*q[j].z + gv.w*q[j].w; \
        } \
        uint4 p0 = { h2pack(q[0].x,q[0].y), h2pack(q[0].z,q[0].w), \
                     h2pack(q[1].x,q[1].y), h2pack(q[1].z,q[1].w) }; \
        uint4 p1 = { h2pack(q[2].x,q[2].y), h2pack(q[2].z,q[2].w), \
                     h2pack(q[3].x,q[3].y), h2pack(q[3].z,q[3].w) }; \
        *(uint4*)(As[(st)] + lr * PADH + h * 16)     = p0; \
        *(uint4*)(As[(st)] + lr * PADH + h * 16 + 8) = p1; \
    } while (0)

    // prologue: tile 0
    if (t >= 256) {
        #pragma unroll
        for (int q = 0; q < 4; q++)
            cp16(Bs[0] + t2 * PADH + q * 8, Bsrc + q * 8);
        CP_COMMIT();
    } else {
        float4 q[4];
        #pragma unroll
        for (int j = 0; j < 4; j++) q[j] = Xr[h * 4 + j];
        G1_APROC(0, 0, q);
    }
    CP_WAIT0();
    __syncthreads();

    #pragma unroll 1
    for (int tt = 0; tt < NT1; ++tt) {
        int buf = tt & 1, nbuf = buf ^ 1;
        float4 q[4];
        if (tt + 1 < NT1) {
            if (t >= 256) {
                const __half* src = Bsrc + (tt + 1) * 32;
                #pragma unroll
                for (int qq = 0; qq < 4; qq++)
                    cp16(Bs[nbuf] + t2 * PADH + qq * 8, src + qq * 8);
                CP_COMMIT();
            } else {
                int kq = (tt + 1) * 8;
                #pragma unroll
                for (int j = 0; j < 4; j++) q[j] = Xr[kq + h * 4 + j];
            }
        }
        #pragma unroll
        for (int ks = 0; ks < 2; ++ks) {
            uint32_t af[4][4], bf[4][2];
            #pragma unroll
            for (int mi = 0; mi < 4; ++mi)
                LDSM4(af[mi][0], af[mi][1], af[mi][2], af[mi][3],
                      sA[buf] + aBase + mi * 16 * PADB + ks * 32);
            #pragma unroll
            for (int ni2 = 0; ni2 < 2; ++ni2) {
                uint32_t r0, r1, r2, r3;
                LDSM4(r0, r1, r2, r3, sB[buf] + bBase + ni2 * 16 * PADB + ks * 32);
                bf[ni2 * 2][0] = r0; bf[ni2 * 2][1] = r1;
                bf[ni2 * 2 + 1][0] = r2; bf[ni2 * 2 + 1][1] = r3;
            }
            #pragma unroll
            for (int mi = 0; mi < 4; ++mi)
                #pragma unroll
                for (int ni = 0; ni < 4; ++ni)
                    MMAF16(acc[mi][ni], af[mi], bf[ni]);
        }
        if (tt + 1 < NT1 && t < 256) {
            G1_APROC(nbuf, tt + 1, q);
        }
        CP_WAIT0();
        __syncthreads();
    }

    // LN stats: 2 staging threads per row
    if (t < 256) {
        s0  += __shfl_xor_sync(0xffffffffu, s0, 1);
        s20 += __shfl_xor_sync(0xffffffffu, s20, 1);
        sg0 += __shfl_xor_sync(0xffffffffu, sg0, 1);
        if (h == 0) {
            float C0 = g_consts[0], C1 = g_consts[1];
            float mean = s0 * (1.f / Dk);
            float var = s20 * (1.f / Dk) - mean * mean;
            float rstd = rsqrtf(var + 1e-5f);
            s_rstd[lr] = rstd;
            s_nmr[lr] = -mean * rstd;
            g_feat[rowBase + lr] = (sg0 - mean * C0) * rstd * (1.f / Dk) + C1 * (1.f / Dk);
        }
    }
    __syncthreads();

    // epilogue -> g_U (fp16)
    #pragma unroll
    for (int ni = 0; ni < 4; ++ni) {
        int cg = n0w + ni * 8 + 2 * tg;
        float ca0 = g_cA[cg], ca1 = g_cA[cg + 1];
        float cb0 = g_cB[cg], cb1 = g_cB[cg + 1];
        #pragma unroll
        for (int mi = 0; mi < 4; ++mi) {
            int r1 = m0w + mi * 16 + g;
            float rs1 = s_rstd[r1], nm1 = s_nmr[r1];
            float rs2 = s_rstd[r1 + 8], nm2 = s_nmr[r1 + 8];
            uint32_t o1 = h2pack(acc[mi][ni][0] * rs1 + nm1 * ca0 + cb0,
                                 acc[mi][ni][1] * rs1 + nm1 * ca1 + cb1);
            uint32_t o2 = h2pack(acc[mi][ni][2] * rs2 + nm2 * ca0 + cb0,
                                 acc[mi][ni][3] * rs2 + nm2 * ca1 + cb1);
            *(uint32_t*)(g_U + (size_t)(rowBase + r1) * Rk + cg) = o1;
            *(uint32_t*)(g_U + (size_t)(rowBase + r1 + 8) * Rk + cg) = o2;
        }
    }
}

// ================= fp16 mma GEMM 2 (R8 verbatim) =================
// out = G[d]*(U @ Wq + bq); tile 128x256, BK=32, K=256, NT=8, 3-stage.
#define GST   30720
#define GSMEM 92160
#define NT2 8
__global__ __launch_bounds__(512, 1) void kGemm2MMA(const float* __restrict__ bq,
                                                    float* __restrict__ out) {
    extern __shared__ char smm[];
    uint32_t sBase = smem_u32(smm);
    int t = threadIdx.x, w = t >> 5, lane = t & 31, g = lane >> 2, tg = lane & 3;
    int rowBase = blockIdx.y * 128, colBase = blockIdx.x * 256;
    int m0w = (w >> 3) * 64, n0w = (w & 7) * 32;

    uint32_t aOff = (uint32_t)((m0w + (lane & 15)) * PADB + (lane >> 4) * 16);
    uint32_t bOff = 10240u + (uint32_t)((n0w + (lane & 7) + ((lane >> 4) << 3)) * PADB
                                        + ((lane >> 3) & 1) * 16);

    int ar = t >> 2, ac = t & 3;
    int br = t >> 1, bc = t & 1;
    const __half* Asrc = g_U + (size_t)(rowBase + ar) * Rk + ac * 8;
    const __half* Bsrc = g_WqT + (size_t)(colBase + br) * Rk + bc * 16;

    #define G2_ISSUE(st, tt) do { \
        char* S = smm + (st) * GST; \
        cp16((__half*)S + ar * PADH + ac * 8, Asrc + (size_t)(tt) * 32); \
        __half* B = (__half*)(S + 10240); \
        const __half* bs = Bsrc + (size_t)(tt) * 32; \
        cp16(B + br * PADH + bc * 16,     bs); \
        cp16(B + br * PADH + bc * 16 + 8, bs + 8); \
        CP_COMMIT(); \
    } while (0)

    float acc[4][4][4] = {};

    G2_ISSUE(0, 0);
    G2_ISSUE(1, 1);
    CP_WAIT1();
    __syncthreads();

    #pragma unroll 1
    for (int tt = 0; tt < NT2; ++tt) {
        if (tt + 2 < NT2) G2_ISSUE((tt + 2) % 3, tt + 2);
        uint32_t sb = sBase + (tt % 3) * GST;
        #pragma unroll
        for (int ks = 0; ks < 2; ++ks) {
            uint32_t af[4][4], bf[4][2];
            #pragma unroll
            for (int mi = 0; mi < 4; ++mi)
                LDSM4(af[mi][0], af[mi][1], af[mi][2], af[mi][3],
                      sb + aOff + mi * 16 * PADB + ks * 32);
            #pragma unroll
            for (int ni2 = 0; ni2 < 2; ++ni2) {
                uint32_t r0, r1, r2, r3;
                LDSM4(r0, r1, r2, r3, sb + bOff + ni2 * 16 * PADB + ks * 32);
                bf[ni2 * 2][0] = r0; bf[ni2 * 2][1] = r1;
                bf[ni2 * 2 + 1][0] = r2; bf[ni2 * 2 + 1][1] = r3;
            }
            #pragma unroll
            for (int mi = 0; mi < 4; ++mi)
                #pragma unroll
                for (int ni = 0; ni < 4; ++ni)
                    MMAF16(acc[mi][ni], af[mi], bf[ni]);
        }
        if (tt + 2 < NT2) { CP_WAIT1(); }
        else if (tt + 1 < NT2) { CP_WAIT0(); }
        __syncthreads();
    }

    #pragma unroll
    for (int ni = 0; ni < 4; ++ni) {
        int cg = colBase + n0w + ni * 8 + 2 * tg;
        float G0 = g_G[cg], G1 = g_G[cg + 1];
        float q0 = bq[cg], q1 = bq[cg + 1];
        #pragma unroll
        for (int mi = 0; mi < 4; ++mi) {
            int r1 = rowBase + m0w + mi * 16 + g;
            float2 o1, o2;
            o1.x = G0 * (acc[mi][ni][0] + q0);
            o1.y = G1 * (acc[mi][ni][1] + q1);
            o2.x = G0 * (acc[mi][ni][2] + q0);
            o2.y = G1 * (acc[mi][ni][3] + q1);
            *(float2*)&out[(size_t)r1 * Dk + cg] = o1;
            *(float2*)&out[(size_t)(r1 + 8) * Dk + cg] = o2;
        }
    }
}

// ---------------- launch ----------------
extern "C" void kernel_launch(void* const* d_in, const int* in_sizes, int n_in,
                              void* d_out, int out_size) {
    const float* x     = (const float*)d_in[0];
    const float* gamma = (const float*)d_in[1];
    const float* beta  = (const float*)d_in[2];
    const float* P     = (const float*)d_in[3];
    const float* dlt   = (const float*)d_in[4];
    const float* phiw  = (const float*)d_in[5];
    const float* phib  = (const float*)d_in[6];
    const float* toep  = (const float*)d_in[7];
    const float* Wq    = (const float*)d_in[8];
    const float* bq    = (const float*)d_in[9];
    const float* glog  = (const float*)d_in[10];
    const int*   step  = (const int*)d_in[11];
    int Kc   = in_sizes[7];
    int glen = in_sizes[10];

    cudaFuncSetAttribute(kGemm1MMA, cudaFuncAttributeMaxDynamicSharedMemorySize, SM1_TOTAL);
    cudaFuncSetAttribute(kGemm2MMA, cudaFuncAttributeMaxDynamicSharedMemorySize, GSMEM);

    kPre1<<<801, 256>>>(gamma, beta, phiw, P, toep, Wq, Kc);
    kEg<<<17, 256>>>(dlt);
    kApPart<<<256, 256>>>(P);
    kComb<<<512, 256>>>(gamma);
    kGemm1MMA<<<128, 512, SM1_TOTAL>>>(x, gamma);
    kScale<<<256, 256>>>(phib, glog, step, glen);
    kGemm2MMA<<<dim3(8, 128), 512, GSMEM>>>(bq, (float*)d_out);
}

// round 11
// speedup vs baseline: 1.1175x; 1.0216x over previous
#include <cuda_runtime.h>
#include <cuda_fp16.h>
#include <cstdint>
#include <math.h>

#define Bk 8
#define Lk 2048
#define Dk 2048
#define Rk 256
#define BLk (Bk * Lk)   // 16384 rows

// ---------------- device scratch ----------------
static __device__ float g_C[Rk * Rk];                 // Toeplitz matrix C[s,i]
static __device__ float g_E[Rk * Rk];                 // E = C @ dlt       (256x256)
static __device__ float g_ApP[2][(size_t)Rk * Dk];    // kAp k-split partials
static __device__ __half g_BT1[Rk * Dk];              // A'^T fp16         (256x2048)
static __device__ __half g_WqT[Dk * Rk];              // Wq^T fp16         (2048x256)
static __device__ __half g_U[(size_t)BLk * Rk];       // z_mixed fp16
static __device__ float g_feat[BLk];
static __device__ float g_pg[Rk], g_pb[Rk];
static __device__ float g_cA[Rk], g_cB[Rk];
static __device__ float g_G[Dk];
static __device__ float g_consts[4];
static __device__ float g_pgp[32 * Rk], g_pbp[32 * Rk];

// ---------------- helpers ----------------
__device__ __forceinline__ uint32_t smem_u32(const void* p) {
    uint32_t a;
    asm("{ .reg .u64 t; cvta.to.shared.u64 t, %1; cvt.u32.u64 %0, t; }" : "=r"(a) : "l"(p));
    return a;
}
__device__ __forceinline__ void cp16(void* dst, const void* src) {
    uint32_t d = smem_u32(dst);
    asm volatile("cp.async.cg.shared.global [%0], [%1], 16;" :: "r"(d), "l"(src) : "memory");
}
#define CP_COMMIT() asm volatile("cp.async.commit_group;" ::: "memory")
#define CP_WAIT0()  asm volatile("cp.async.wait_group 0;" ::: "memory")
#define CP_WAIT1()  asm volatile("cp.async.wait_group 1;" ::: "memory")

#define LDSM4(r0, r1, r2, r3, addr) \
    asm volatile("ldmatrix.sync.aligned.m8n8.x4.shared.b16 {%0,%1,%2,%3}, [%4];" \
        : "=r"(r0), "=r"(r1), "=r"(r2), "=r"(r3) : "r"(addr))

#define MMAF16(c, a, b) \
    asm volatile( \
        "mma.sync.aligned.m16n8k16.row.col.f32.f16.f16.f32 " \
        "{%0,%1,%2,%3},{%4,%5,%6,%7},{%8,%9},{%0,%1,%2,%3};" \
        : "+f"((c)[0]), "+f"((c)[1]), "+f"((c)[2]), "+f"((c)[3]) \
        : "r"((a)[0]), "r"((a)[1]), "r"((a)[2]), "r"((a)[3]), \
          "r"((b)[0]), "r"((b)[1]))

__device__ __forceinline__ uint32_t h2pack(float a, float b) {
    __half2 h = __floats2half2_rn(a, b);
    return *reinterpret_cast<uint32_t*>(&h);
}

__device__ __forceinline__ float blockReduce256(float v, float* sm) {
    int t = threadIdx.x;
    sm[t] = v;
    __syncthreads();
    #pragma unroll
    for (int off = 128; off > 0; off >>= 1) {
        if (t < off) sm[t] += sm[t + off];
        __syncthreads();
    }
    float r = sm[0];
    __syncthreads();
    return r;
}

// pad-40-halves row layout (80 bytes): ldmatrix phases conflict-free.
#define PADH 40
#define PADB 80

// ================= fused precompute 1 =================
// bid 0: consts; 1..32: pgb partials; 33..288: build C; 289..800: WqT transpose
__global__ __launch_bounds__(256) void kPre1(const float* __restrict__ gamma,
                                             const float* __restrict__ beta,
                                             const float* __restrict__ phiw,
                                             const float* __restrict__ P,
                                             const float* __restrict__ toep,
                                             const float* __restrict__ Wq, int Kc) {
    int bid = blockIdx.x, t = threadIdx.x;
    if (bid == 0) {
        __shared__ float sm[256];
        float a = 0.f, b = 0.f, c = 0.f;
        for (int j = t; j < Dk; j += 256) { a += gamma[j]; b += beta[j]; }
        for (int j = t; j < Rk; j += 256) { c += phiw[j]; }
        float A = blockReduce256(a, sm);
        float B = blockReduce256(b, sm);
        float C = blockReduce256(c, sm);
        if (t == 0) { g_consts[0] = A; g_consts[1] = B; g_consts[2] = C; }
    } else if (bid <= 32) {
        int chunk = bid - 1;
        float ag = 0.f, ab = 0.f;
        #pragma unroll 4
        for (int j = 0; j < 64; j++) {
            int d = chunk * 64 + j;
            float p = P[(size_t)d * Rk + t];
            ag += gamma[d] * p;
            ab += beta[d] * p;
        }
        g_pgp[chunk * Rk + t] = ag;
        g_pbp[chunk * Rk + t] = ab;
    } else if (bid <= 288) {
        int s = bid - 33;
        int pad = (Kc - 1) >> 1;
        int idx = t - s + pad;
        g_C[s * Rk + t] = (idx >= 0 && idx < Kc) ? toep[idx] : 0.f;
    } else {
        int id = bid - 289;
        int bx = id & 63, by = id >> 6;
        __shared__ float tile[32][33];
        int tx = t & 31, ty8 = t >> 5;
        #pragma unroll
        for (int i = 0; i < 32; i += 8)
            tile[ty8 + i][tx] = Wq[(size_t)(by * 32 + ty8 + i) * Dk + bx * 32 + tx];
        __syncthreads();
        #pragma unroll
        for (int i = 0; i < 32; i += 8)
            g_WqT[(size_t)(bx * 32 + ty8 + i) * Rk + by * 32 + tx] =
                __float2half_rn(tile[tx][ty8 + i]);
    }
}

// ================= kEg: E = C @ dlt + pgb2 reduce =================
__global__ __launch_bounds__(256) void kEg(const float* __restrict__ dlt) {
    int bid = blockIdx.x, t = threadIdx.x;
    if (bid == 16) {
        float a = 0.f, b = 0.f;
        #pragma unroll
        for (int c = 0; c < 32; c++) { a += g_pgp[c * Rk + t]; b += g_pbp[c * Rk + t]; }
        g_pg[t] = a;
        g_pb[t] = b;
        return;
    }
    __shared__ float Cs[16][66];
    __shared__ float Ds[16][68];
    int bx = bid & 3, by = bid >> 2;
    int sBase = by * 64, rBase = bx * 64;
    int ty = t >> 4, tx = t & 15;
    float acc[4][4] = {};
    for (int k0 = 0; k0 < Rk; k0 += 16) {
        {
            int m = t >> 2, kq = (t & 3) * 4;
            float4 v = *(const float4*)&g_C[(size_t)(sBase + m) * Rk + k0 + kq];
            Cs[kq + 0][m] = v.x; Cs[kq + 1][m] = v.y; Cs[kq + 2][m] = v.z; Cs[kq + 3][m] = v.w;
        }
        {
            int kk = t >> 4, n4 = (t & 15) * 4;
            float4 v = *(const float4*)&dlt[(size_t)(k0 + kk) * Rk + rBase + n4];
            *(float4*)&Ds[kk][n4] = v;
        }
        __syncthreads();
        #pragma unroll
        for (int k = 0; k < 16; k++) {
            float a[4], b[4];
            #pragma unroll
            for (int i = 0; i < 4; i++) a[i] = Cs[k][ty * 4 + i];
            #pragma unroll
            for (int j = 0; j < 4; j++) b[j] = Ds[k][tx * 4 + j];
            #pragma unroll
            for (int i = 0; i < 4; i++)
                #pragma unroll
                for (int j = 0; j < 4; j++) acc[i][j] += a[i] * b[j];
        }
        __syncthreads();
    }
    #pragma unroll
    for (int i = 0; i < 4; i++)
        #pragma unroll
        for (int j = 0; j < 4; j++)
            g_E[(size_t)(sBase + ty * 4 + i) * Rk + rBase + tx * 4 + j] = acc[i][j];
}

// ================= kApPart: partial A'^T over half of K =================
__global__ __launch_bounds__(256) void kApPart(const float* __restrict__ P) {
    __shared__ __align__(16) float Ps[16][64];
    __shared__ __align__(16) float Es[16][68];
    int bid = blockIdx.x, t = threadIdx.x;
    int kh = bid >> 7;
    int rem = bid & 127;
    int bx = rem & 3, by = rem >> 2;
    int dBase = by * 64, sBase = bx * 64, kBase = kh * 128;
    int ty = t >> 4, tx = t & 15;
    float acc[4][4] = {};
    for (int c = 0; c < 8; c++) {
        int k0 = kBase + c * 16;
        {
            int m = t >> 2, kq = (t & 3) * 4;
            float4 v = *(const float4*)&P[(size_t)(dBase + m) * Rk + k0 + kq];
            Ps[kq + 0][m] = v.x; Ps[kq + 1][m] = v.y; Ps[kq + 2][m] = v.z; Ps[kq + 3][m] = v.w;
            float4 e = *(const float4*)&g_E[(size_t)(sBase + m) * Rk + k0 + kq];
            Es[kq + 0][m] = e.x; Es[kq + 1][m] = e.y; Es[kq + 2][m] = e.z; Es[kq + 3][m] = e.w;
        }
        __syncthreads();
        #pragma unroll
        for (int k = 0; k < 16; k++) {
            float4 av = *(const float4*)&Ps[k][ty * 4];
            float4 bv = *(const float4*)&Es[k][tx * 4];
            float a[4] = { av.x, av.y, av.z, av.w };
            float b[4] = { bv.x, bv.y, bv.z, bv.w };
            #pragma unroll
            for (int i = 0; i < 4; i++)
                #pragma unroll
                for (int j = 0; j < 4; j++) acc[i][j] += a[i] * b[j];
        }
        __syncthreads();
    }
    #pragma unroll
    for (int j = 0; j < 4; j++) {
        int s = sBase + tx * 4 + j;
        float4 o = { acc[0][j], acc[1][j], acc[2][j], acc[3][j] };
        *(float4*)&g_ApP[kh][(size_t)s * Dk + dBase + ty * 4] = o;
    }
}

// ================= kComb: BT1 = fp16(gamma*(p0+p1)); cA/cB =================
__global__ __launch_bounds__(256) void kComb(const float* __restrict__ gamma) {
    int bid = blockIdx.x, t = threadIdx.x;
    if (bid >= 256) {
        __shared__ float sm[256];
        int s = bid - 256;
        float e = g_E[(size_t)s * Rk + t];
        float ca = blockReduce256(g_pg[t] * e, sm);
        float cb = blockReduce256(g_pb[t] * e, sm);
        if (t == 0) { g_cA[s] = ca; g_cB[s] = cb; }
        return;
    }
    int s = bid;
    #pragma unroll
    for (int it = 0; it < 2; it++) {
        int d0 = it * 1024 + t * 4;
        float4 p0 = *(const float4*)&g_ApP[0][(size_t)s * Dk + d0];
        float4 p1 = *(const float4*)&g_ApP[1][(size_t)s * Dk + d0];
        float4 gv = *(const float4*)&gamma[d0];
        uint2 pk;
        pk.x = h2pack(gv.x * (p0.x + p1.x), gv.y * (p0.y + p1.y));
        pk.y = h2pack(gv.z * (p0.z + p1.z), gv.w * (p0.w + p1.w));
        *(uint2*)&g_BT1[(size_t)s * Dk + d0] = pk;
    }
}

// G[l] = sigmoid(g_logit[..]) * scale[l]  (needs g_feat from GEMM1)
__global__ void kScale(const float* __restrict__ phib, const float* __restrict__ glog,
                       const int* __restrict__ step_p, int glen) {
    int w = threadIdx.x >> 5, lane = threadIdx.x & 31;
    int l = blockIdx.x * 8 + w;
    const float PI_F = 3.14159274101257324f;
    float base = PI_F * ((float)l + 0.5f);
    float c1 = 0.f, c2 = 0.f;
    #pragma unroll
    for (int j = 0; j < 8; j++) {
        int r = lane + 32 * j;
        c1 += cosf((base * (float)r) / (float)Lk);
        c2 += phib[(size_t)l * Rk + r];
    }
    float c3 = (lane < Bk) ? g_feat[(size_t)lane * Lk + l] : 0.f;
    #pragma unroll
    for (int o = 16; o > 0; o >>= 1) {
        c1 += __shfl_xor_sync(0xffffffffu, c1, o);
        c2 += __shfl_xor_sync(0xffffffffu, c2, o);
        c3 += __shfl_xor_sync(0xffffffffu, c3, o);
    }
    if (lane == 0) {
        int step = *step_p;
        float det_scale = fminf((float)((double)step / 2000.0), 1.0f);
        float scale = det_scale * (c1 / (float)Rk) + (c2 / (float)Rk)
                    + (c3 / (float)Bk) * (g_consts[2] / (float)Rk);
        int gi = l / (Dk / glen);
        float gs = 1.0f / (1.0f + expf(-glog[gi]));
        g_G[l] = gs * scale;
    }
}

// ================= fp16 mma GEMM 1 — TRUE R5 version (94.2us measured) ==========
// U = (X @ A')*rstd + nmr*cA + cB; M=16384, N=256, K=2048. BK=32, NT=64,
// grid 128 (X read once), 512 thr. Warps 0-7 stage A (2 thr/row, 16 floats each,
// fp32->fp16 + LN stats), warps 8-15 stage B (cp.async). All compute 64x32 tiles.
#define NT1 64
#define SM1_AS0   0
#define SM1_AS1   10240
#define SM1_BS0   20480
#define SM1_BS1   40960
#define SM1_GAM   61440
#define SM1_RSTD  69632
#define SM1_NMR   70144
#define SM1_TOTAL 70656

__global__ __launch_bounds__(512) void kGemm1MMA(const float* __restrict__ X,
                                                 const float* __restrict__ gamma) {
    extern __shared__ char sm1[];
    __half* As[2] = { (__half*)(sm1 + SM1_AS0), (__half*)(sm1 + SM1_AS1) };
    __half* Bs[2] = { (__half*)(sm1 + SM1_BS0), (__half*)(sm1 + SM1_BS1) };
    float* s_gam  = (float*)(sm1 + SM1_GAM);
    float* s_rstd = (float*)(sm1 + SM1_RSTD);
    float* s_nmr  = (float*)(sm1 + SM1_NMR);

    int t = threadIdx.x, w = t >> 5, lane = t & 31, g = lane >> 2, tg = lane & 3;
    int rowBase = blockIdx.x * 128;
    int m0w = (w >> 3) * 64, n0w = (w & 7) * 32;

    for (int i = t; i < Dk / 4; i += 512)
        ((float4*)s_gam)[i] = ((const float4*)gamma)[i];

    uint32_t sA[2] = { smem_u32(As[0]), smem_u32(As[1]) };
    uint32_t sB[2] = { smem_u32(Bs[0]), smem_u32(Bs[1]) };
    uint32_t aBase = (uint32_t)((m0w + (lane & 15)) * PADB + (lane >> 4) * 16);
    uint32_t bBase = (uint32_t)((n0w + (lane & 7) + ((lane >> 4) << 3)) * PADB
                                + ((lane >> 3) & 1) * 16);

    int lr = t >> 1, h = t & 1;   // A stagers: row (0..127), 16-float half
    int t2 = t & 255;             // B stagers row
    const float4* Xr = (const float4*)(X + (size_t)(rowBase + lr) * Dk);
    const __half* Bsrc = g_BT1 + (size_t)t2 * Dk;

    float acc[4][4][4] = {};
    float s0 = 0.f, s20 = 0.f, sg0 = 0.f;

    __syncthreads();  // gamma visible

    #define G1_APROC(st, tt, q) do { \
        _Pragma("unroll") \
        for (int j = 0; j < 4; j++) { \
            float4 gv = ((const float4*)s_gam)[(tt) * 8 + h * 4 + j]; \
            s0  += (q[j].x + q[j].y) + (q[j].z + q[j].w); \
            s20 += q[j].x*q[j].x + q[j].y*q[j].y + q[j].z*q[j].z + q[j].w*q[j].w; \
            sg0 += gv.x*q[j].x + gv.y*q[j].y + gv.z*q[j].z + gv.w*q[j].w; \
        } \
        uint4 p0 = { h2pack(q[0].x,q[0].y), h2pack(q[0].z,q[0].w), \
                     h2pack(q[1].x,q[1].y), h2pack(q[1].z,q[1].w) }; \
        uint4 p1 = { h2pack(q[2].x,q[2].y), h2pack(q[2].z,q[2].w), \
                     h2pack(q[3].x,q[3].y), h2pack(q[3].z,q[3].w) }; \
        *(uint4*)(As[(st)] + lr * PADH + h * 16)     = p0; \
        *(uint4*)(As[(st)] + lr * PADH + h * 16 + 8) = p1; \
    } while (0)

    // prologue: tile 0
    if (t >= 256) {
        #pragma unroll
        for (int q = 0; q < 4; q++)
            cp16(Bs[0] + t2 * PADH + q * 8, Bsrc + q * 8);
        CP_COMMIT();
    } else {
        float4 q[4];
        #pragma unroll
        for (int j = 0; j < 4; j++) q[j] = Xr[h * 4 + j];
        G1_APROC(0, 0, q);
    }
    CP_WAIT0();
    __syncthreads();

    #pragma unroll 1
    for (int tt = 0; tt < NT1; ++tt) {
        int buf = tt & 1, nbuf = buf ^ 1;
        float4 q[4];
        if (tt + 1 < NT1) {
            if (t >= 256) {
                const __half* src = Bsrc + (tt + 1) * 32;
                #pragma unroll
                for (int qq = 0; qq < 4; qq++)
                    cp16(Bs[nbuf] + t2 * PADH + qq * 8, src + qq * 8);
                CP_COMMIT();
            } else {
                int kq = (tt + 1) * 8;
                #pragma unroll
                for (int j = 0; j < 4; j++) q[j] = Xr[kq + h * 4 + j];
            }
        }
        #pragma unroll
        for (int ks = 0; ks < 2; ++ks) {
            uint32_t af[4][4], bf[4][2];
            #pragma unroll
            for (int mi = 0; mi < 4; ++mi)
                LDSM4(af[mi][0], af[mi][1], af[mi][2], af[mi][3],
                      sA[buf] + aBase + mi * 16 * PADB + ks * 32);
            #pragma unroll
            for (int ni2 = 0; ni2 < 2; ++ni2) {
                uint32_t r0, r1, r2, r3;
                LDSM4(r0, r1, r2, r3, sB[buf] + bBase + ni2 * 16 * PADB + ks * 32);
                bf[ni2 * 2][0] = r0; bf[ni2 * 2][1] = r1;
                bf[ni2 * 2 + 1][0] = r2; bf[ni2 * 2 + 1][1] = r3;
            }
            #pragma unroll
            for (int mi = 0; mi < 4; ++mi)
                #pragma unroll
                for (int ni = 0; ni < 4; ++ni)
                    MMAF16(acc[mi][ni], af[mi], bf[ni]);
        }
        if (tt + 1 < NT1 && t < 256) {
            G1_APROC(nbuf, tt + 1, q);
        }
        CP_WAIT0();
        __syncthreads();
    }

    // LN stats: 2 staging threads per row
    if (t < 256) {
        s0  += __shfl_xor_sync(0xffffffffu, s0, 1);
        s20 += __shfl_xor_sync(0xffffffffu, s20, 1);
        sg0 += __shfl_xor_sync(0xffffffffu, sg0, 1);
        if (h == 0) {
            float C0 = g_consts[0], C1 = g_consts[1];
            float mean = s0 * (1.f / Dk);
            float var = s20 * (1.f / Dk) - mean * mean;
            float rstd = rsqrtf(var + 1e-5f);
            s_rstd[lr] = rstd;
            s_nmr[lr] = -mean * rstd;
            g_feat[rowBase + lr] = (sg0 - mean * C0) * rstd * (1.f / Dk) + C1 * (1.f / Dk);
        }
    }
    __syncthreads();

    // epilogue -> g_U (fp16)
    #pragma unroll
    for (int ni = 0; ni < 4; ++ni) {
        int cg = n0w + ni * 8 + 2 * tg;
        float ca0 = g_cA[cg], ca1 = g_cA[cg + 1];
        float cb0 = g_cB[cg], cb1 = g_cB[cg + 1];
        #pragma unroll
        for (int mi = 0; mi < 4; ++mi) {
            int r1 = m0w + mi * 16 + g;
            float rs1 = s_rstd[r1], nm1 = s_nmr[r1];
            float rs2 = s_rstd[r1 + 8], nm2 = s_nmr[r1 + 8];
            uint32_t o1 = h2pack(acc[mi][ni][0] * rs1 + nm1 * ca0 + cb0,
                                 acc[mi][ni][1] * rs1 + nm1 * ca1 + cb1);
            uint32_t o2 = h2pack(acc[mi][ni][2] * rs2 + nm2 * ca0 + cb0,
                                 acc[mi][ni][3] * rs2 + nm2 * ca1 + cb1);
            *(uint32_t*)(g_U + (size_t)(rowBase + r1) * Rk + cg) = o1;
            *(uint32_t*)(g_U + (size_t)(rowBase + r1 + 8) * Rk + cg) = o2;
        }
    }
}

// ================= fp16 mma GEMM 2 — TRUE R5 version (128-col, 256-thr) =========
// out = G[d]*(U @ Wq + bq); M=16384, N=2048, K=256. grid (16,128), 256 thr,
// CTA tile 128x128, warp tile 64x32, BK=32, NT=8, 3-stage cp.async pipeline.
#define NT2 8
#define SM2_STAGE 20480   // bytes per stage (A 10240 + B 10240)
#define SM2_TOTAL 61440

__global__ __launch_bounds__(256) void kGemm2MMA(const float* __restrict__ bq,
                                                 float* __restrict__ out) {
    extern __shared__ char sm2[];
    int t = threadIdx.x, w = t >> 5, lane = t & 31, g = lane >> 2, tg = lane & 3;
    int rowBase = blockIdx.y * 128, colBase = blockIdx.x * 128;
    int m0w = (w >> 2) * 64, n0w = (w & 3) * 32;

    uint32_t sBase0 = smem_u32(sm2);
    uint32_t aBase = (uint32_t)((m0w + (lane & 15)) * PADB + (lane >> 4) * 16);
    uint32_t bBase = 10240u + (uint32_t)((n0w + (lane & 7) + ((lane >> 4) << 3)) * PADB
                                         + ((lane >> 3) & 1) * 16);

    int lr = t >> 1, h = t & 1;
    const __half* Asrc = g_U + (size_t)(rowBase + lr) * Rk + h * 16;
    const __half* Bsrc = g_WqT + (size_t)(colBase + lr) * Rk + h * 16;

    float acc[4][4][4] = {};

    #define G2_ISSUE(st, tt) do { \
        __half* A = (__half*)(sm2 + (st) * SM2_STAGE); \
        __half* B = (__half*)(sm2 + (st) * SM2_STAGE + 10240); \
        cp16(A + lr * PADH + h * 16,     Asrc + (tt) * 32); \
        cp16(A + lr * PADH + h * 16 + 8, Asrc + (tt) * 32 + 8); \
        cp16(B + lr * PADH + h * 16,     Bsrc + (tt) * 32); \
        cp16(B + lr * PADH + h * 16 + 8, Bsrc + (tt) * 32 + 8); \
        CP_COMMIT(); \
    } while (0)

    G2_ISSUE(0, 0);
    G2_ISSUE(1, 1);
    CP_WAIT1();
    __syncthreads();

    #pragma unroll 1
    for (int tt = 0; tt < NT2; ++tt) {
        int st = tt % 3;
        uint32_t sb = sBase0 + st * SM2_STAGE;
        #pragma unroll
        for (int ks = 0; ks < 2; ++ks) {
            uint32_t af[4][4], bf[4][2];
            #pragma unroll
            for (int mi = 0; mi < 4; ++mi)
                LDSM4(af[mi][0], af[mi][1], af[mi][2], af[mi][3],
                      sb + aBase + mi * 16 * PADB + ks * 32);
            #pragma unroll
            for (int ni2 = 0; ni2 < 2; ++ni2) {
                uint32_t r0, r1, r2, r3;
                LDSM4(r0, r1, r2, r3, sb + bBase + ni2 * 16 * PADB + ks * 32);
                bf[ni2 * 2][0] = r0; bf[ni2 * 2][1] = r1;
                bf[ni2 * 2 + 1][0] = r2; bf[ni2 * 2 + 1][1] = r3;
            }
            #pragma unroll
            for (int mi = 0; mi < 4; ++mi)
                #pragma unroll
                for (int ni = 0; ni < 4; ++ni)
                    MMAF16(acc[mi][ni], af[mi], bf[ni]);
        }
        if (tt + 2 < NT2) {
            G2_ISSUE((tt + 2) % 3, tt + 2);
            CP_WAIT1();
        } else if (tt + 1 < NT2) {
            CP_WAIT0();
        }
        __syncthreads();
    }

    #pragma unroll
    for (int ni = 0; ni < 4; ++ni) {
        int cg = colBase + n0w + ni * 8 + 2 * tg;
        float G0 = g_G[cg], G1 = g_G[cg + 1];
        float q0 = bq[cg], q1 = bq[cg + 1];
        #pragma unroll
        for (int mi = 0; mi < 4; ++mi) {
            int r1 = rowBase + m0w + mi * 16 + g;
            float2 o1, o2;
            o1.x = G0 * (acc[mi][ni][0] + q0);
            o1.y = G1 * (acc[mi][ni][1] + q1);
            o2.x = G0 * (acc[mi][ni][2] + q0);
            o2.y = G1 * (acc[mi][ni][3] + q1);
            *(float2*)&out[(size_t)r1 * Dk + cg] = o1;
            *(float2*)&out[(size_t)(r1 + 8) * Dk + cg] = o2;
        }
    }
}

// ---------------- launch ----------------
extern "C" void kernel_launch(void* const* d_in, const int* in_sizes, int n_in,
                              void* d_out, int out_size) {
    const float* x     = (const float*)d_in[0];
    const float* gamma = (const float*)d_in[1];
    const float* beta  = (const float*)d_in[2];
    const float* P     = (const float*)d_in[3];
    const float* dlt   = (const float*)d_in[4];
    const float* phiw  = (const float*)d_in[5];
    const float* phib  = (const float*)d_in[6];
    const float* toep  = (const float*)d_in[7];
    const float* Wq    = (const float*)d_in[8];
    const float* bq    = (const float*)d_in[9];
    const float* glog  = (const float*)d_in[10];
    const int*   step  = (const int*)d_in[11];
    int Kc   = in_sizes[7];
    int glen = in_sizes[10];

    cudaFuncSetAttribute(kGemm1MMA, cudaFuncAttributeMaxDynamicSharedMemorySize, SM1_TOTAL);
    cudaFuncSetAttribute(kGemm2MMA, cudaFuncAttributeMaxDynamicSharedMemorySize, SM2_TOTAL);

    kPre1<<<801, 256>>>(gamma, beta, phiw, P, toep, Wq, Kc);
    kEg<<<17, 256>>>(dlt);
    kApPart<<<256, 256>>>(P);
    kComb<<<512, 256>>>(gamma);
    kGemm1MMA<<<128, 512, SM1_TOTAL>>>(x, gamma);
    kScale<<<256, 256>>>(phib, glog, step, glen);
    kGemm2MMA<<<dim3(16, 128), 256, SM2_TOTAL>>>(bq, (float*)d_out);
}

// round 12
// speedup vs baseline: 1.1654x; 1.0428x over previous
#include <cuda_runtime.h>
#include <cuda_fp16.h>
#include <cstdint>
#include <math.h>

#define Bk 8
#define Lk 2048
#define Dk 2048
#define Rk 256
#define BLk (Bk * Lk)   // 16384 rows

// ---------------- device scratch ----------------
static __device__ float g_C[Rk * Rk];                 // Toeplitz matrix C[s,i]
static __device__ float g_E[Rk * Rk];                 // E = C @ dlt fp32  (256x256)
static __device__ __half g_Eh[Rk * Rk];               // E fp16
static __device__ __half g_Ph[Dk * Rk];               // P fp16 (d-major, r-contig)
static __device__ __half g_BT1[Rk * Dk];              // A'^T fp16         (256x2048)
static __device__ __half g_WqT[Dk * Rk];              // Wq^T fp16         (2048x256)
static __device__ __half g_U[(size_t)BLk * Rk];       // z_mixed fp16
static __device__ float g_feat[BLk];
static __device__ float g_pg[Rk], g_pb[Rk];
static __device__ float g_cA[Rk], g_cB[Rk];
static __device__ float g_G[Dk];
static __device__ float g_consts[4];
static __device__ float g_pgp[32 * Rk], g_pbp[32 * Rk];

// ---------------- helpers ----------------
__device__ __forceinline__ uint32_t smem_u32(const void* p) {
    uint32_t a;
    asm("{ .reg .u64 t; cvta.to.shared.u64 t, %1; cvt.u32.u64 %0, t; }" : "=r"(a) : "l"(p));
    return a;
}
__device__ __forceinline__ void cp16(void* dst, const void* src) {
    uint32_t d = smem_u32(dst);
    asm volatile("cp.async.cg.shared.global [%0], [%1], 16;" :: "r"(d), "l"(src) : "memory");
}
#define CP_COMMIT() asm volatile("cp.async.commit_group;" ::: "memory")
#define CP_WAIT0()  asm volatile("cp.async.wait_group 0;" ::: "memory")
#define CP_WAIT1()  asm volatile("cp.async.wait_group 1;" ::: "memory")

#define LDSM4(r0, r1, r2, r3, addr) \
    asm volatile("ldmatrix.sync.aligned.m8n8.x4.shared.b16 {%0,%1,%2,%3}, [%4];" \
        : "=r"(r0), "=r"(r1), "=r"(r2), "=r"(r3) : "r"(addr))

#define MMAF16(c, a, b) \
    asm volatile( \
        "mma.sync.aligned.m16n8k16.row.col.f32.f16.f16.f32 " \
        "{%0,%1,%2,%3},{%4,%5,%6,%7},{%8,%9},{%0,%1,%2,%3};" \
        : "+f"((c)[0]), "+f"((c)[1]), "+f"((c)[2]), "+f"((c)[3]) \
        : "r"((a)[0]), "r"((a)[1]), "r"((a)[2]), "r"((a)[3]), \
          "r"((b)[0]), "r"((b)[1]))

__device__ __forceinline__ uint32_t h2pack(float a, float b) {
    __half2 h = __floats2half2_rn(a, b);
    return *reinterpret_cast<uint32_t*>(&h);
}

__device__ __forceinline__ float blockReduce256(float v, float* sm) {
    int t = threadIdx.x;
    sm[t] = v;
    __syncthreads();
    #pragma unroll
    for (int off = 128; off > 0; off >>= 1) {
        if (t < off) sm[t] += sm[t + off];
        __syncthreads();
    }
    float r = sm[0];
    __syncthreads();
    return r;
}

// pad-40-halves row layout (80 bytes): ldmatrix phases conflict-free.
#define PADH 40
#define PADB 80

// ================= fused precompute 1 =================
// bid 0: consts; 1..32: pgb partials; 33..288: build C; 289..800: WqT transpose;
// 801..864: Ph = fp16(P)
__global__ __launch_bounds__(256) void kPre1(const float* __restrict__ gamma,
                                             const float* __restrict__ beta,
                                             const float* __restrict__ phiw,
                                             const float* __restrict__ P,
                                             const float* __restrict__ toep,
                                             const float* __restrict__ Wq, int Kc) {
    int bid = blockIdx.x, t = threadIdx.x;
    if (bid == 0) {
        __shared__ float sm[256];
        float a = 0.f, b = 0.f, c = 0.f;
        for (int j = t; j < Dk; j += 256) { a += gamma[j]; b += beta[j]; }
        for (int j = t; j < Rk; j += 256) { c += phiw[j]; }
        float A = blockReduce256(a, sm);
        float B = blockReduce256(b, sm);
        float C = blockReduce256(c, sm);
        if (t == 0) { g_consts[0] = A; g_consts[1] = B; g_consts[2] = C; }
    } else if (bid <= 32) {
        int chunk = bid - 1;
        float ag = 0.f, ab = 0.f;
        #pragma unroll 4
        for (int j = 0; j < 64; j++) {
            int d = chunk * 64 + j;
            float p = P[(size_t)d * Rk + t];
            ag += gamma[d] * p;
            ab += beta[d] * p;
        }
        g_pgp[chunk * Rk + t] = ag;
        g_pbp[chunk * Rk + t] = ab;
    } else if (bid <= 288) {
        int s = bid - 33;
        int pad = (Kc - 1) >> 1;
        int idx = t - s + pad;
        g_C[s * Rk + t] = (idx >= 0 && idx < Kc) ? toep[idx] : 0.f;
    } else if (bid <= 800) {
        int id = bid - 289;
        int bx = id & 63, by = id >> 6;
        __shared__ float tile[32][33];
        int tx = t & 31, ty8 = t >> 5;
        #pragma unroll
        for (int i = 0; i < 32; i += 8)
            tile[ty8 + i][tx] = Wq[(size_t)(by * 32 + ty8 + i) * Dk + bx * 32 + tx];
        __syncthreads();
        #pragma unroll
        for (int i = 0; i < 32; i += 8)
            g_WqT[(size_t)(bx * 32 + ty8 + i) * Rk + by * 32 + tx] =
                __float2half_rn(tile[tx][ty8 + i]);
    } else {
        // Ph = fp16(P): 64 blocks x 8192 elems
        int base = (bid - 801) * 8192;
        #pragma unroll
        for (int i = 0; i < 8; i++) {
            int idx = base + i * 1024 + t * 4;
            float4 v = *(const float4*)&P[idx];
            uint2 pk = { h2pack(v.x, v.y), h2pack(v.z, v.w) };
            *(uint2*)&g_Ph[idx] = pk;
        }
    }
}

// ================= kEg: E = C @ dlt (fp32 + fp16 copies) + pgb2 reduce ==========
__global__ __launch_bounds__(256) void kEg(const float* __restrict__ dlt) {
    int bid = blockIdx.x, t = threadIdx.x;
    if (bid == 16) {
        float a = 0.f, b = 0.f;
        #pragma unroll
        for (int c = 0; c < 32; c++) { a += g_pgp[c * Rk + t]; b += g_pbp[c * Rk + t]; }
        g_pg[t] = a;
        g_pb[t] = b;
        return;
    }
    __shared__ float Cs[16][66];
    __shared__ float Ds[16][68];
    int bx = bid & 3, by = bid >> 2;
    int sBase = by * 64, rBase = bx * 64;
    int ty = t >> 4, tx = t & 15;
    float acc[4][4] = {};
    for (int k0 = 0; k0 < Rk; k0 += 16) {
        {
            int m = t >> 2, kq = (t & 3) * 4;
            float4 v = *(const float4*)&g_C[(size_t)(sBase + m) * Rk + k0 + kq];
            Cs[kq + 0][m] = v.x; Cs[kq + 1][m] = v.y; Cs[kq + 2][m] = v.z; Cs[kq + 3][m] = v.w;
        }
        {
            int kk = t >> 4, n4 = (t & 15) * 4;
            float4 v = *(const float4*)&dlt[(size_t)(k0 + kk) * Rk + rBase + n4];
            *(float4*)&Ds[kk][n4] = v;
        }
        __syncthreads();
        #pragma unroll
        for (int k = 0; k < 16; k++) {
            float a[4], b[4];
            #pragma unroll
            for (int i = 0; i < 4; i++) a[i] = Cs[k][ty * 4 + i];
            #pragma unroll
            for (int j = 0; j < 4; j++) b[j] = Ds[k][tx * 4 + j];
            #pragma unroll
            for (int i = 0; i < 4; i++)
                #pragma unroll
                for (int j = 0; j < 4; j++) acc[i][j] += a[i] * b[j];
        }
        __syncthreads();
    }
    #pragma unroll
    for (int i = 0; i < 4; i++) {
        int s = sBase + ty * 4 + i;
        #pragma unroll
        for (int j = 0; j < 4; j++) {
            int r = rBase + tx * 4 + j;
            g_E[(size_t)s * Rk + r] = acc[i][j];
            g_Eh[(size_t)s * Rk + r] = __float2half_rn(acc[i][j]);
        }
    }
}

// ================= kApMMA: BT1[s][d] = fp16(gamma[d] * (Eh @ Ph^T)) + cA/cB =====
// mma: M=256 (s rows), N=2048 (d cols), K=256. CTA tile 128x128, BK=32, 3-stage.
// bid < 32: mma tile (by = bid>>4 row tile, bx = bid&15 col tile).
// bid 32..287: cA/cB reduction for s = bid-32 (uses fp32 g_E).
#define NTA 8
#define SMA_STAGE 20480
#define SMA_TOTAL 61440

__global__ __launch_bounds__(256) void kApMMA(const float* __restrict__ gamma) {
    extern __shared__ char sma[];
    int bid = blockIdx.x, t = threadIdx.x;
    if (bid >= 32) {
        __shared__ float sm[256];
        int s = bid - 32;
        float e = g_E[(size_t)s * Rk + t];
        float ca = blockReduce256(g_pg[t] * e, sm);
        float cb = blockReduce256(g_pb[t] * e, sm);
        if (t == 0) { g_cA[s] = ca; g_cB[s] = cb; }
        return;
    }
    int w = t >> 5, lane = t & 31, g = lane >> 2, tg = lane & 3;
    int rowBase = (bid >> 4) * 128;   // s
    int colBase = (bid & 15) * 128;   // d
    int m0w = (w >> 2) * 64, n0w = (w & 3) * 32;

    uint32_t sBase0 = smem_u32(sma);
    uint32_t aBase = (uint32_t)((m0w + (lane & 15)) * PADB + (lane >> 4) * 16);
    uint32_t bBase = 10240u + (uint32_t)((n0w + (lane & 7) + ((lane >> 4) << 3)) * PADB
                                         + ((lane >> 3) & 1) * 16);

    int lr = t >> 1, h = t & 1;
    const __half* Asrc = g_Eh + (size_t)(rowBase + lr) * Rk + h * 16;
    const __half* Bsrc = g_Ph + (size_t)(colBase + lr) * Rk + h * 16;

    float acc[4][4][4] = {};

    #define GA_ISSUE(st, tt) do { \
        __half* A = (__half*)(sma + (st) * SMA_STAGE); \
        __half* B = (__half*)(sma + (st) * SMA_STAGE + 10240); \
        cp16(A + lr * PADH + h * 16,     Asrc + (tt) * 32); \
        cp16(A + lr * PADH + h * 16 + 8, Asrc + (tt) * 32 + 8); \
        cp16(B + lr * PADH + h * 16,     Bsrc + (tt) * 32); \
        cp16(B + lr * PADH + h * 16 + 8, Bsrc + (tt) * 32 + 8); \
        CP_COMMIT(); \
    } while (0)

    GA_ISSUE(0, 0);
    GA_ISSUE(1, 1);
    CP_WAIT1();
    __syncthreads();

    #pragma unroll 1
    for (int tt = 0; tt < NTA; ++tt) {
        int st = tt % 3;
        uint32_t sb = sBase0 + st * SMA_STAGE;
        #pragma unroll
        for (int ks = 0; ks < 2; ++ks) {
            uint32_t af[4][4], bf[4][2];
            #pragma unroll
            for (int mi = 0; mi < 4; ++mi)
                LDSM4(af[mi][0], af[mi][1], af[mi][2], af[mi][3],
                      sb + aBase + mi * 16 * PADB + ks * 32);
            #pragma unroll
            for (int ni2 = 0; ni2 < 2; ++ni2) {
                uint32_t r0, r1, r2, r3;
                LDSM4(r0, r1, r2, r3, sb + bBase + ni2 * 16 * PADB + ks * 32);
                bf[ni2 * 2][0] = r0; bf[ni2 * 2][1] = r1;
                bf[ni2 * 2 + 1][0] = r2; bf[ni2 * 2 + 1][1] = r3;
            }
            #pragma unroll
            for (int mi = 0; mi < 4; ++mi)
                #pragma unroll
                for (int ni = 0; ni < 4; ++ni)
                    MMAF16(acc[mi][ni], af[mi], bf[ni]);
        }
        if (tt + 2 < NTA) {
            GA_ISSUE((tt + 2) % 3, tt + 2);
            CP_WAIT1();
        } else if (tt + 1 < NTA) {
            CP_WAIT0();
        }
        __syncthreads();
    }

    #pragma unroll
    for (int ni = 0; ni < 4; ++ni) {
        int cg = colBase + n0w + ni * 8 + 2 * tg;
        float ga0 = gamma[cg], ga1 = gamma[cg + 1];
        #pragma unroll
        for (int mi = 0; mi < 4; ++mi) {
            int s1 = rowBase + m0w + mi * 16 + g;
            *(uint32_t*)&g_BT1[(size_t)s1 * Dk + cg] =
                h2pack(ga0 * acc[mi][ni][0], ga1 * acc[mi][ni][1]);
            *(uint32_t*)&g_BT1[(size_t)(s1 + 8) * Dk + cg] =
                h2pack(ga0 * acc[mi][ni][2], ga1 * acc[mi][ni][3]);
        }
    }
}

// G[l] = sigmoid(g_logit[..]) * scale[l]  (needs g_feat from GEMM1)
__global__ void kScale(const float* __restrict__ phib, const float* __restrict__ glog,
                       const int* __restrict__ step_p, int glen) {
    int w = threadIdx.x >> 5, lane = threadIdx.x & 31;
    int l = blockIdx.x * 8 + w;
    const float PI_F = 3.14159274101257324f;
    float base = PI_F * ((float)l + 0.5f);
    float c1 = 0.f, c2 = 0.f;
    #pragma unroll
    for (int j = 0; j < 8; j++) {
        int r = lane + 32 * j;
        c1 += cosf((base * (float)r) / (float)Lk);
        c2 += phib[(size_t)l * Rk + r];
    }
    float c3 = (lane < Bk) ? g_feat[(size_t)lane * Lk + l] : 0.f;
    #pragma unroll
    for (int o = 16; o > 0; o >>= 1) {
        c1 += __shfl_xor_sync(0xffffffffu, c1, o);
        c2 += __shfl_xor_sync(0xffffffffu, c2, o);
        c3 += __shfl_xor_sync(0xffffffffu, c3, o);
    }
    if (lane == 0) {
        int step = *step_p;
        float det_scale = fminf((float)((double)step / 2000.0), 1.0f);
        float scale = det_scale * (c1 / (float)Rk) + (c2 / (float)Rk)
                    + (c3 / (float)Bk) * (g_consts[2] / (float)Rk);
        int gi = l / (Dk / glen);
        float gs = 1.0f / (1.0f + expf(-glog[gi]));
        g_G[l] = gs * scale;
    }
}

// ================= fp16 mma GEMM 1 — R5 version (94.2us measured) ===============
#define NT1 64
#define SM1_AS0   0
#define SM1_AS1   10240
#define SM1_BS0   20480
#define SM1_BS1   40960
#define SM1_GAM   61440
#define SM1_RSTD  69632
#define SM1_NMR   70144
#define SM1_TOTAL 70656

__global__ __launch_bounds__(512) void kGemm1MMA(const float* __restrict__ X,
                                                 const float* __restrict__ gamma) {
    extern __shared__ char sm1[];
    __half* As[2] = { (__half*)(sm1 + SM1_AS0), (__half*)(sm1 + SM1_AS1) };
    __half* Bs[2] = { (__half*)(sm1 + SM1_BS0), (__half*)(sm1 + SM1_BS1) };
    float* s_gam  = (float*)(sm1 + SM1_GAM);
    float* s_rstd = (float*)(sm1 + SM1_RSTD);
    float* s_nmr  = (float*)(sm1 + SM1_NMR);

    int t = threadIdx.x, w = t >> 5, lane = t & 31, g = lane >> 2, tg = lane & 3;
    int rowBase = blockIdx.x * 128;
    int m0w = (w >> 3) * 64, n0w = (w & 7) * 32;

    for (int i = t; i < Dk / 4; i += 512)
        ((float4*)s_gam)[i] = ((const float4*)gamma)[i];

    uint32_t sA[2] = { smem_u32(As[0]), smem_u32(As[1]) };
    uint32_t sB[2] = { smem_u32(Bs[0]), smem_u32(Bs[1]) };
    uint32_t aBase = (uint32_t)((m0w + (lane & 15)) * PADB + (lane >> 4) * 16);
    uint32_t bBase = (uint32_t)((n0w + (lane & 7) + ((lane >> 4) << 3)) * PADB
                                + ((lane >> 3) & 1) * 16);

    int lr = t >> 1, h = t & 1;   // A stagers: row (0..127), 16-float half
    int t2 = t & 255;             // B stagers row
    const float4* Xr = (const float4*)(X + (size_t)(rowBase + lr) * Dk);
    const __half* Bsrc = g_BT1 + (size_t)t2 * Dk;

    float acc[4][4][4] = {};
    float s0 = 0.f, s20 = 0.f, sg0 = 0.f;

    __syncthreads();  // gamma visible

    #define G1_APROC(st, tt, q) do { \
        _Pragma("unroll") \
        for (int j = 0; j < 4; j++) { \
            float4 gv = ((const float4*)s_gam)[(tt) * 8 + h * 4 + j]; \
            s0  += (q[j].x + q[j].y) + (q[j].z + q[j].w); \
            s20 += q[j].x*q[j].x + q[j].y*q[j].y + q[j].z*q[j].z + q[j].w*q[j].w; \
            sg0 += gv.x*q[j].x + gv.y*q[j].y + gv.z*q[j].z + gv.w*q[j].w; \
        } \
        uint4 p0 = { h2pack(q[0].x,q[0].y), h2pack(q[0].z,q[0].w), \
                     h2pack(q[1].x,q[1].y), h2pack(q[1].z,q[1].w) }; \
        uint4 p1 = { h2pack(q[2].x,q[2].y), h2pack(q[2].z,q[2].w), \
                     h2pack(q[3].x,q[3].y), h2pack(q[3].z,q[3].w) }; \
        *(uint4*)(As[(st)] + lr * PADH + h * 16)     = p0; \
        *(uint4*)(As[(st)] + lr * PADH + h * 16 + 8) = p1; \
    } while (0)

    // prologue: tile 0
    if (t >= 256) {
        #pragma unroll
        for (int q = 0; q < 4; q++)
            cp16(Bs[0] + t2 * PADH + q * 8, Bsrc + q * 8);
        CP_COMMIT();
    } else {
        float4 q[4];
        #pragma unroll
        for (int j = 0; j < 4; j++) q[j] = Xr[h * 4 + j];
        G1_APROC(0, 0, q);
    }
    CP_WAIT0();
    __syncthreads();

    #pragma unroll 1
    for (int tt = 0; tt < NT1; ++tt) {
        int buf = tt & 1, nbuf = buf ^ 1;
        float4 q[4];
        if (tt + 1 < NT1) {
            if (t >= 256) {
                const __half* src = Bsrc + (tt + 1) * 32;
                #pragma unroll
                for (int qq = 0; qq < 4; qq++)
                    cp16(Bs[nbuf] + t2 * PADH + qq * 8, src + qq * 8);
                CP_COMMIT();
            } else {
                int kq = (tt + 1) * 8;
                #pragma unroll
                for (int j = 0; j < 4; j++) q[j] = Xr[kq + h * 4 + j];
            }
        }
        #pragma unroll
        for (int ks = 0; ks < 2; ++ks) {
            uint32_t af[4][4], bf[4][2];
            #pragma unroll
            for (int mi = 0; mi < 4; ++mi)
                LDSM4(af[mi][0], af[mi][1], af[mi][2], af[mi][3],
                      sA[buf] + aBase + mi * 16 * PADB + ks * 32);
            #pragma unroll
            for (int ni2 = 0; ni2 < 2; ++ni2) {
                uint32_t r0, r1, r2, r3;
                LDSM4(r0, r1, r2, r3, sB[buf] + bBase + ni2 * 16 * PADB + ks * 32);
                bf[ni2 * 2][0] = r0; bf[ni2 * 2][1] = r1;
                bf[ni2 * 2 + 1][0] = r2; bf[ni2 * 2 + 1][1] = r3;
            }
            #pragma unroll
            for (int mi = 0; mi < 4; ++mi)
                #pragma unroll
                for (int ni = 0; ni < 4; ++ni)
                    MMAF16(acc[mi][ni], af[mi], bf[ni]);
        }
        if (tt + 1 < NT1 && t < 256) {
            G1_APROC(nbuf, tt + 1, q);
        }
        CP_WAIT0();
        __syncthreads();
    }

    // LN stats: 2 staging threads per row
    if (t < 256) {
        s0  += __shfl_xor_sync(0xffffffffu, s0, 1);
        s20 += __shfl_xor_sync(0xffffffffu, s20, 1);
        sg0 += __shfl_xor_sync(0xffffffffu, sg0, 1);
        if (h == 0) {
            float C0 = g_consts[0], C1 = g_consts[1];
            float mean = s0 * (1.f / Dk);
            float var = s20 * (1.f / Dk) - mean * mean;
            float rstd = rsqrtf(var + 1e-5f);
            s_rstd[lr] = rstd;
            s_nmr[lr] = -mean * rstd;
            g_feat[rowBase + lr] = (sg0 - mean * C0) * rstd * (1.f / Dk) + C1 * (1.f / Dk);
        }
    }
    __syncthreads();

    // epilogue -> g_U (fp16)
    #pragma unroll
    for (int ni = 0; ni < 4; ++ni) {
        int cg = n0w + ni * 8 + 2 * tg;
        float ca0 = g_cA[cg], ca1 = g_cA[cg + 1];
        float cb0 = g_cB[cg], cb1 = g_cB[cg + 1];
        #pragma unroll
        for (int mi = 0; mi < 4; ++mi) {
            int r1 = m0w + mi * 16 + g;
            float rs1 = s_rstd[r1], nm1 = s_nmr[r1];
            float rs2 = s_rstd[r1 + 8], nm2 = s_nmr[r1 + 8];
            uint32_t o1 = h2pack(acc[mi][ni][0] * rs1 + nm1 * ca0 + cb0,
                                 acc[mi][ni][1] * rs1 + nm1 * ca1 + cb1);
            uint32_t o2 = h2pack(acc[mi][ni][2] * rs2 + nm2 * ca0 + cb0,
                                 acc[mi][ni][3] * rs2 + nm2 * ca1 + cb1);
            *(uint32_t*)(g_U + (size_t)(rowBase + r1) * Rk + cg) = o1;
            *(uint32_t*)(g_U + (size_t)(rowBase + r1 + 8) * Rk + cg) = o2;
        }
    }
}

// ================= fp16 mma GEMM 2 — R5 version (128-col, 256-thr) ==============
#define NT2 8
#define SM2_STAGE 20480
#define SM2_TOTAL 61440

__global__ __launch_bounds__(256) void kGemm2MMA(const float* __restrict__ bq,
                                                 float* __restrict__ out) {
    extern __shared__ char sm2[];
    int t = threadIdx.x, w = t >> 5, lane = t & 31, g = lane >> 2, tg = lane & 3;
    int rowBase = blockIdx.y * 128, colBase = blockIdx.x * 128;
    int m0w = (w >> 2) * 64, n0w = (w & 3) * 32;

    uint32_t sBase0 = smem_u32(sm2);
    uint32_t aBase = (uint32_t)((m0w + (lane & 15)) * PADB + (lane >> 4) * 16);
    uint32_t bBase = 10240u + (uint32_t)((n0w + (lane & 7) + ((lane >> 4) << 3)) * PADB
                                         + ((lane >> 3) & 1) * 16);

    int lr = t >> 1, h = t & 1;
    const __half* Asrc = g_U + (size_t)(rowBase + lr) * Rk + h * 16;
    const __half* Bsrc = g_WqT + (size_t)(colBase + lr) * Rk + h * 16;

    float acc[4][4][4] = {};

    #define G2_ISSUE(st, tt) do { \
        __half* A = (__half*)(sm2 + (st) * SM2_STAGE); \
        __half* B = (__half*)(sm2 + (st) * SM2_STAGE + 10240); \
        cp16(A + lr * PADH + h * 16,     Asrc + (tt) * 32); \
        cp16(A + lr * PADH + h * 16 + 8, Asrc + (tt) * 32 + 8); \
        cp16(B + lr * PADH + h * 16,     Bsrc + (tt) * 32); \
        cp16(B + lr * PADH + h * 16 + 8, Bsrc + (tt) * 32 + 8); \
        CP_COMMIT(); \
    } while (0)

    G2_ISSUE(0, 0);
    G2_ISSUE(1, 1);
    CP_WAIT1();
    __syncthreads();

    #pragma unroll 1
    for (int tt = 0; tt < NT2; ++tt) {
        int st = tt % 3;
        uint32_t sb = sBase0 + st * SM2_STAGE;
        #pragma unroll
        for (int ks = 0; ks < 2; ++ks) {
            uint32_t af[4][4], bf[4][2];
            #pragma unroll
            for (int mi = 0; mi < 4; ++mi)
                LDSM4(af[mi][0], af[mi][1], af[mi][2], af[mi][3],
                      sb + aBase + mi * 16 * PADB + ks * 32);
            #pragma unroll
            for (int ni2 = 0; ni2 < 2; ++ni2) {
                uint32_t r0, r1, r2, r3;
                LDSM4(r0, r1, r2, r3, sb + bBase + ni2 * 16 * PADB + ks * 32);
                bf[ni2 * 2][0] = r0; bf[ni2 * 2][1] = r1;
                bf[ni2 * 2 + 1][0] = r2; bf[ni2 * 2 + 1][1] = r3;
            }
            #pragma unroll
            for (int mi = 0; mi < 4; ++mi)
                #pragma unroll
                for (int ni = 0; ni < 4; ++ni)
                    MMAF16(acc[mi][ni], af[mi], bf[ni]);
        }
        if (tt + 2 < NT2) {
            G2_ISSUE((tt + 2) % 3, tt + 2);
            CP_WAIT1();
        } else if (tt + 1 < NT2) {
            CP_WAIT0();
        }
        __syncthreads();
    }

    #pragma unroll
    for (int ni = 0; ni < 4; ++ni) {
        int cg = colBase + n0w + ni * 8 + 2 * tg;
        float G0 = g_G[cg], G1 = g_G[cg + 1];
        float q0 = bq[cg], q1 = bq[cg + 1];
        #pragma unroll
        for (int mi = 0; mi < 4; ++mi) {
            int r1 = rowBase + m0w + mi * 16 + g;
            float2 o1, o2;
            o1.x = G0 * (acc[mi][ni][0] + q0);
            o1.y = G1 * (acc[mi][ni][1] + q1);
            o2.x = G0 * (acc[mi][ni][2] + q0);
            o2.y = G1 * (acc[mi][ni][3] + q1);
            *(float2*)&out[(size_t)r1 * Dk + cg] = o1;
            *(float2*)&out[(size_t)(r1 + 8) * Dk + cg] = o2;
        }
    }
}

// ---------------- launch ----------------
extern "C" void kernel_launch(void* const* d_in, const int* in_sizes, int n_in,
                              void* d_out, int out_size) {
    const float* x     = (const float*)d_in[0];
    const float* gamma = (const float*)d_in[1];
    const float* beta  = (const float*)d_in[2];
    const float* P     = (const float*)d_in[3];
    const float* dlt   = (const float*)d_in[4];
    const float* phiw  = (const float*)d_in[5];
    const float* phib  = (const float*)d_in[6];
    const float* toep  = (const float*)d_in[7];
    const float* Wq    = (const float*)d_in[8];
    const float* bq    = (const float*)d_in[9];
    const float* glog  = (const float*)d_in[10];
    const int*   step  = (const int*)d_in[11];
    int Kc   = in_sizes[7];
    int glen = in_sizes[10];

    cudaFuncSetAttribute(kApMMA,    cudaFuncAttributeMaxDynamicSharedMemorySize, SMA_TOTAL);
    cudaFuncSetAttribute(kGemm1MMA, cudaFuncAttributeMaxDynamicSharedMemorySize, SM1_TOTAL);
    cudaFuncSetAttribute(kGemm2MMA, cudaFuncAttributeMaxDynamicSharedMemorySize, SM2_TOTAL);

    kPre1<<<865, 256>>>(gamma, beta, phiw, P, toep, Wq, Kc);
    kEg<<<17, 256>>>(dlt);
    kApMMA<<<288, 256, SMA_TOTAL>>>(gamma);
    kGemm1MMA<<<128, 512, SM1_TOTAL>>>(x, gamma);
    kScale<<<256, 256>>>(phib, glog, step, glen);
    kGemm2MMA<<<dim3(16, 128), 256, SM2_TOTAL>>>(bq, (float*)d_out);
}

// round 13
// speedup vs baseline: 1.2102x; 1.0385x over previous
#include <cuda_runtime.h>
#include <cuda_fp16.h>
#include <cstdint>
#include <math.h>

#define Bk 8
#define Lk 2048
#define Dk 2048
#define Rk 256
#define BLk (Bk * Lk)   // 16384 rows

// ---------------- device scratch ----------------
static __device__ float g_C[Rk * Rk];                 // Toeplitz matrix C[s,i]
static __device__ float g_E[Rk * Rk];                 // E = C @ dlt fp32  (256x256)
static __device__ __half g_Eh[Rk * Rk];               // E fp16
static __device__ __half g_Ph[Dk * Rk];               // P fp16 (d-major, r-contig)
static __device__ __half g_BT1[Rk * Dk];              // A'^T fp16         (256x2048)
static __device__ __half g_WqT[Dk * Rk];              // Wq^T fp16         (2048x256)
static __device__ __half g_U[(size_t)BLk * Rk];       // z_mixed fp16
static __device__ float g_feat[BLk];
static __device__ float g_pg[Rk], g_pb[Rk];
static __device__ float g_cA[Rk], g_cB[Rk];
static __device__ float g_G[Dk];
static __device__ float g_consts[4];
static __device__ float g_pgp[32 * Rk], g_pbp[32 * Rk];

// ---------------- helpers ----------------
__device__ __forceinline__ uint32_t smem_u32(const void* p) {
    uint32_t a;
    asm("{ .reg .u64 t; cvta.to.shared.u64 t, %1; cvt.u32.u64 %0, t; }" : "=r"(a) : "l"(p));
    return a;
}
__device__ __forceinline__ void cp16(void* dst, const void* src) {
    uint32_t d = smem_u32(dst);
    asm volatile("cp.async.cg.shared.global [%0], [%1], 16;" :: "r"(d), "l"(src) : "memory");
}
#define CP_COMMIT() asm volatile("cp.async.commit_group;" ::: "memory")
#define CP_WAIT0()  asm volatile("cp.async.wait_group 0;" ::: "memory")
#define CP_WAIT1()  asm volatile("cp.async.wait_group 1;" ::: "memory")

#define LDSM4(r0, r1, r2, r3, addr) \
    asm volatile("ldmatrix.sync.aligned.m8n8.x4.shared.b16 {%0,%1,%2,%3}, [%4];" \
        : "=r"(r0), "=r"(r1), "=r"(r2), "=r"(r3) : "r"(addr))

#define MMAF16(c, a, b) \
    asm volatile( \
        "mma.sync.aligned.m16n8k16.row.col.f32.f16.f16.f32 " \
        "{%0,%1,%2,%3},{%4,%5,%6,%7},{%8,%9},{%0,%1,%2,%3};" \
        : "+f"((c)[0]), "+f"((c)[1]), "+f"((c)[2]), "+f"((c)[3]) \
        : "r"((a)[0]), "r"((a)[1]), "r"((a)[2]), "r"((a)[3]), \
          "r"((b)[0]), "r"((b)[1]))

__device__ __forceinline__ uint32_t h2pack(float a, float b) {
    __half2 h = __floats2half2_rn(a, b);
    return *reinterpret_cast<uint32_t*>(&h);
}

__device__ __forceinline__ float blockReduce256(float v, float* sm) {
    int t = threadIdx.x;
    sm[t] = v;
    __syncthreads();
    #pragma unroll
    for (int off = 128; off > 0; off >>= 1) {
        if (t < off) sm[t] += sm[t + off];
        __syncthreads();
    }
    float r = sm[0];
    __syncthreads();
    return r;
}

// pad-40-halves row layout (80 bytes): ldmatrix phases conflict-free.
#define PADH 40
#define PADB 80

// ================= fused precompute 1 =================
// bid 0: consts; 1..32: pgb partials; 33..288: build C; 289..800: WqT transpose;
// 801..864: Ph = fp16(P)
__global__ __launch_bounds__(256) void kPre1(const float* __restrict__ gamma,
                                             const float* __restrict__ beta,
                                             const float* __restrict__ phiw,
                                             const float* __restrict__ P,
                                             const float* __restrict__ toep,
                                             const float* __restrict__ Wq, int Kc) {
    int bid = blockIdx.x, t = threadIdx.x;
    if (bid == 0) {
        __shared__ float sm[256];
        float a = 0.f, b = 0.f, c = 0.f;
        for (int j = t; j < Dk; j += 256) { a += gamma[j]; b += beta[j]; }
        for (int j = t; j < Rk; j += 256) { c += phiw[j]; }
        float A = blockReduce256(a, sm);
        float B = blockReduce256(b, sm);
        float C = blockReduce256(c, sm);
        if (t == 0) { g_consts[0] = A; g_consts[1] = B; g_consts[2] = C; }
    } else if (bid <= 32) {
        int chunk = bid - 1;
        float ag = 0.f, ab = 0.f;
        #pragma unroll 4
        for (int j = 0; j < 64; j++) {
            int d = chunk * 64 + j;
            float p = P[(size_t)d * Rk + t];
            ag += gamma[d] * p;
            ab += beta[d] * p;
        }
        g_pgp[chunk * Rk + t] = ag;
        g_pbp[chunk * Rk + t] = ab;
    } else if (bid <= 288) {
        int s = bid - 33;
        int pad = (Kc - 1) >> 1;
        int idx = t - s + pad;
        g_C[s * Rk + t] = (idx >= 0 && idx < Kc) ? toep[idx] : 0.f;
    } else if (bid <= 800) {
        int id = bid - 289;
        int bx = id & 63, by = id >> 6;
        __shared__ float tile[32][33];
        int tx = t & 31, ty8 = t >> 5;
        #pragma unroll
        for (int i = 0; i < 32; i += 8)
            tile[ty8 + i][tx] = Wq[(size_t)(by * 32 + ty8 + i) * Dk + bx * 32 + tx];
        __syncthreads();
        #pragma unroll
        for (int i = 0; i < 32; i += 8)
            g_WqT[(size_t)(bx * 32 + ty8 + i) * Rk + by * 32 + tx] =
                __float2half_rn(tile[tx][ty8 + i]);
    } else {
        // Ph = fp16(P): 64 blocks x 8192 elems
        int base = (bid - 801) * 8192;
        #pragma unroll
        for (int i = 0; i < 8; i++) {
            int idx = base + i * 1024 + t * 4;
            float4 v = *(const float4*)&P[idx];
            uint2 pk = { h2pack(v.x, v.y), h2pack(v.z, v.w) };
            *(uint2*)&g_Ph[idx] = pk;
        }
    }
}

// ================= kEg: E = C @ dlt (fp32 + fp16) + pgb2. 32x64 tiles, grid 33 ==
__global__ __launch_bounds__(256) void kEg(const float* __restrict__ dlt) {
    int bid = blockIdx.x, t = threadIdx.x;
    if (bid == 32) {
        float a = 0.f, b = 0.f;
        #pragma unroll
        for (int c = 0; c < 32; c++) { a += g_pgp[c * Rk + t]; b += g_pbp[c * Rk + t]; }
        g_pg[t] = a;
        g_pb[t] = b;
        return;
    }
    __shared__ float Cs[16][34];
    __shared__ float Ds[16][68];
    int bx = bid & 3, by = bid >> 2;
    int sBase = by * 32, rBase = bx * 64;
    int ty = t >> 4, tx = t & 15;
    float acc[2][4] = {};
    for (int k0 = 0; k0 < Rk; k0 += 16) {
        {
            int m = t >> 3, kq = (t & 7) * 2;
            float2 v = *(const float2*)&g_C[(size_t)(sBase + m) * Rk + k0 + kq];
            Cs[kq][m] = v.x; Cs[kq + 1][m] = v.y;
        }
        {
            int kk = t >> 4, n4 = (t & 15) * 4;
            float4 v = *(const float4*)&dlt[(size_t)(k0 + kk) * Rk + rBase + n4];
            *(float4*)&Ds[kk][n4] = v;
        }
        __syncthreads();
        #pragma unroll
        for (int k = 0; k < 16; k++) {
            float a0 = Cs[k][ty * 2], a1 = Cs[k][ty * 2 + 1];
            float b[4];
            #pragma unroll
            for (int j = 0; j < 4; j++) b[j] = Ds[k][tx * 4 + j];
            #pragma unroll
            for (int j = 0; j < 4; j++) { acc[0][j] += a0 * b[j]; acc[1][j] += a1 * b[j]; }
        }
        __syncthreads();
    }
    #pragma unroll
    for (int i = 0; i < 2; i++) {
        int s = sBase + ty * 2 + i;
        #pragma unroll
        for (int j = 0; j < 4; j++) {
            int r = rBase + tx * 4 + j;
            g_E[(size_t)s * Rk + r] = acc[i][j];
            g_Eh[(size_t)s * Rk + r] = __float2half_rn(acc[i][j]);
        }
    }
}

// ================= kApMMA: BT1[s][d] = fp16(gamma[d] * (Eh @ Ph^T)) + cA/cB =====
#define NTA 8
#define SMA_STAGE 20480
#define SMA_TOTAL 61440

__global__ __launch_bounds__(256) void kApMMA(const float* __restrict__ gamma) {
    extern __shared__ char sma[];
    int bid = blockIdx.x, t = threadIdx.x;
    if (bid >= 32) {
        __shared__ float sm[256];
        int s = bid - 32;
        float e = g_E[(size_t)s * Rk + t];
        float ca = blockReduce256(g_pg[t] * e, sm);
        float cb = blockReduce256(g_pb[t] * e, sm);
        if (t == 0) { g_cA[s] = ca; g_cB[s] = cb; }
        return;
    }
    int w = t >> 5, lane = t & 31, g = lane >> 2, tg = lane & 3;
    int rowBase = (bid >> 4) * 128;   // s
    int colBase = (bid & 15) * 128;   // d
    int m0w = (w >> 2) * 64, n0w = (w & 3) * 32;

    uint32_t sBase0 = smem_u32(sma);
    uint32_t aBase = (uint32_t)((m0w + (lane & 15)) * PADB + (lane >> 4) * 16);
    uint32_t bBase = 10240u + (uint32_t)((n0w + (lane & 7) + ((lane >> 4) << 3)) * PADB
                                         + ((lane >> 3) & 1) * 16);

    int lr = t >> 1, h = t & 1;
    const __half* Asrc = g_Eh + (size_t)(rowBase + lr) * Rk + h * 16;
    const __half* Bsrc = g_Ph + (size_t)(colBase + lr) * Rk + h * 16;

    float acc[4][4][4] = {};

    #define GA_ISSUE(st, tt) do { \
        __half* A = (__half*)(sma + (st) * SMA_STAGE); \
        __half* B = (__half*)(sma + (st) * SMA_STAGE + 10240); \
        cp16(A + lr * PADH + h * 16,     Asrc + (tt) * 32); \
        cp16(A + lr * PADH + h * 16 + 8, Asrc + (tt) * 32 + 8); \
        cp16(B + lr * PADH + h * 16,     Bsrc + (tt) * 32); \
        cp16(B + lr * PADH + h * 16 + 8, Bsrc + (tt) * 32 + 8); \
        CP_COMMIT(); \
    } while (0)

    GA_ISSUE(0, 0);
    GA_ISSUE(1, 1);
    CP_WAIT1();
    __syncthreads();

    #pragma unroll 1
    for (int tt = 0; tt < NTA; ++tt) {
        int st = tt % 3;
        uint32_t sb = sBase0 + st * SMA_STAGE;
        #pragma unroll
        for (int ks = 0; ks < 2; ++ks) {
            uint32_t af[4][4], bf[4][2];
            #pragma unroll
            for (int mi = 0; mi < 4; ++mi)
                LDSM4(af[mi][0], af[mi][1], af[mi][2], af[mi][3],
                      sb + aBase + mi * 16 * PADB + ks * 32);
            #pragma unroll
            for (int ni2 = 0; ni2 < 2; ++ni2) {
                uint32_t r0, r1, r2, r3;
                LDSM4(r0, r1, r2, r3, sb + bBase + ni2 * 16 * PADB + ks * 32);
                bf[ni2 * 2][0] = r0; bf[ni2 * 2][1] = r1;
                bf[ni2 * 2 + 1][0] = r2; bf[ni2 * 2 + 1][1] = r3;
            }
            #pragma unroll
            for (int mi = 0; mi < 4; ++mi)
                #pragma unroll
                for (int ni = 0; ni < 4; ++ni)
                    MMAF16(acc[mi][ni], af[mi], bf[ni]);
        }
        if (tt + 2 < NTA) {
            GA_ISSUE((tt + 2) % 3, tt + 2);
            CP_WAIT1();
        } else if (tt + 1 < NTA) {
            CP_WAIT0();
        }
        __syncthreads();
    }

    #pragma unroll
    for (int ni = 0; ni < 4; ++ni) {
        int cg = colBase + n0w + ni * 8 + 2 * tg;
        float ga0 = gamma[cg], ga1 = gamma[cg + 1];
        #pragma unroll
        for (int mi = 0; mi < 4; ++mi) {
            int s1 = rowBase + m0w + mi * 16 + g;
            *(uint32_t*)&g_BT1[(size_t)s1 * Dk + cg] =
                h2pack(ga0 * acc[mi][ni][0], ga1 * acc[mi][ni][1]);
            *(uint32_t*)&g_BT1[(size_t)(s1 + 8) * Dk + cg] =
                h2pack(ga0 * acc[mi][ni][2], ga1 * acc[mi][ni][3]);
        }
    }
}

// G[l] = sigmoid(g_logit[..]) * scale[l]  (needs g_feat from GEMM1)
__global__ void kScale(const float* __restrict__ phib, const float* __restrict__ glog,
                       const int* __restrict__ step_p, int glen) {
    int w = threadIdx.x >> 5, lane = threadIdx.x & 31;
    int l = blockIdx.x * 8 + w;
    const float PI_F = 3.14159274101257324f;
    float base = PI_F * ((float)l + 0.5f);
    float c1 = 0.f, c2 = 0.f;
    #pragma unroll
    for (int j = 0; j < 8; j++) {
        int r = lane + 32 * j;
        c1 += cosf((base * (float)r) / (float)Lk);
        c2 += phib[(size_t)l * Rk + r];
    }
    float c3 = (lane < Bk) ? g_feat[(size_t)lane * Lk + l] : 0.f;
    #pragma unroll
    for (int o = 16; o > 0; o >>= 1) {
        c1 += __shfl_xor_sync(0xffffffffu, c1, o);
        c2 += __shfl_xor_sync(0xffffffffu, c2, o);
        c3 += __shfl_xor_sync(0xffffffffu, c3, o);
    }
    if (lane == 0) {
        int step = *step_p;
        float det_scale = fminf((float)((double)step / 2000.0), 1.0f);
        float scale = det_scale * (c1 / (float)Rk) + (c2 / (float)Rk)
                    + (c3 / (float)Bk) * (g_consts[2] / (float)Rk);
        int gi = l / (Dk / glen);
        float gs = 1.0f / (1.0f + expf(-glog[gi]));
        g_G[l] = gs * scale;
    }
}

// ================= fp16 mma GEMM 1 — R5 base + triple-buffered B ================
// U = (X @ A')*rstd + nmr*cA + cB; M=16384, N=256, K=2048. BK=32, NT=64,
// grid 128 (X read once), 512 thr. Warps 0-7 stage A (2 thr/row, fp32->fp16 +
// LN stats, double-buffer STS), warps 8-15 stage B (cp.async, 3 stages, wait1).
#define NT1 64
#define SM1_AS0   0
#define SM1_AS1   10240
#define SM1_BS    20480   // 3 stages x 20480
#define SM1_BST   20480
#define SM1_GAM   81920
#define SM1_RSTD  90112
#define SM1_NMR   90624
#define SM1_TOTAL 91136

__global__ __launch_bounds__(512) void kGemm1MMA(const float* __restrict__ X,
                                                 const float* __restrict__ gamma) {
    extern __shared__ char sm1[];
    __half* As[2] = { (__half*)(sm1 + SM1_AS0), (__half*)(sm1 + SM1_AS1) };
    float* s_gam  = (float*)(sm1 + SM1_GAM);
    float* s_rstd = (float*)(sm1 + SM1_RSTD);
    float* s_nmr  = (float*)(sm1 + SM1_NMR);

    int t = threadIdx.x, w = t >> 5, lane = t & 31, g = lane >> 2, tg = lane & 3;
    int rowBase = blockIdx.x * 128;
    int m0w = (w >> 3) * 64, n0w = (w & 7) * 32;

    for (int i = t; i < Dk / 4; i += 512)
        ((float4*)s_gam)[i] = ((const float4*)gamma)[i];

    uint32_t sA[2] = { smem_u32(As[0]), smem_u32(As[1]) };
    uint32_t sBbase = smem_u32(sm1 + SM1_BS);
    uint32_t aBase = (uint32_t)((m0w + (lane & 15)) * PADB + (lane >> 4) * 16);
    uint32_t bBase = (uint32_t)((n0w + (lane & 7) + ((lane >> 4) << 3)) * PADB
                                + ((lane >> 3) & 1) * 16);

    int lr = t >> 1, h = t & 1;   // A stagers: row (0..127), 16-float half
    int t2 = t & 255;             // B stagers row
    const float4* Xr = (const float4*)(X + (size_t)(rowBase + lr) * Dk);
    const __half* Bsrc = g_BT1 + (size_t)t2 * Dk;

    float acc[4][4][4] = {};
    float s0 = 0.f, s20 = 0.f, sg0 = 0.f;

    __syncthreads();  // gamma visible

    #define G1_APROC(st, tt, q) do { \
        _Pragma("unroll") \
        for (int j = 0; j < 4; j++) { \
            float4 gv = ((const float4*)s_gam)[(tt) * 8 + h * 4 + j]; \
            s0  += (q[j].x + q[j].y) + (q[j].z + q[j].w); \
            s20 += q[j].x*q[j].x + q[j].y*q[j].y + q[j].z*q[j].z + q[j].w*q[j].w; \
            sg0 += gv.x*q[j].x + gv.y*q[j].y + gv.z*q[j].z + gv.w*q[j].w; \
        } \
        uint4 p0 = { h2pack(q[0].x,q[0].y), h2pack(q[0].z,q[0].w), \
                     h2pack(q[1].x,q[1].y), h2pack(q[1].z,q[1].w) }; \
        uint4 p1 = { h2pack(q[2].x,q[2].y), h2pack(q[2].z,q[2].w), \
                     h2pack(q[3].x,q[3].y), h2pack(q[3].z,q[3].w) }; \
        *(uint4*)(As[(st)] + lr * PADH + h * 16)     = p0; \
        *(uint4*)(As[(st)] + lr * PADH + h * 16 + 8) = p1; \
    } while (0)

    #define G1_BISSUE(st, tt) do { \
        __half* B = (__half*)(sm1 + SM1_BS + (st) * SM1_BST); \
        const __half* src = Bsrc + (tt) * 32; \
        cp16(B + t2 * PADH + 0,  src); \
        cp16(B + t2 * PADH + 8,  src + 8); \
        cp16(B + t2 * PADH + 16, src + 16); \
        cp16(B + t2 * PADH + 24, src + 24); \
        CP_COMMIT(); \
    } while (0)

    // prologue: A tile0 -> As[0]; B tiles 0,1 -> stages 0,1
    if (t >= 256) {
        G1_BISSUE(0, 0);
        G1_BISSUE(1, 1);
    } else {
        float4 q[4];
        #pragma unroll
        for (int j = 0; j < 4; j++) q[j] = Xr[h * 4 + j];
        G1_APROC(0, 0, q);
    }
    CP_WAIT1();
    __syncthreads();

    #pragma unroll 1
    for (int tt = 0; tt < NT1; ++tt) {
        float4 q[4];
        if (t >= 256) {
            if (tt + 2 < NT1) G1_BISSUE((tt + 2) % 3, tt + 2);
        } else if (tt + 1 < NT1) {
            int kq = (tt + 1) * 8;
            #pragma unroll
            for (int j = 0; j < 4; j++) q[j] = Xr[kq + h * 4 + j];
        }
        {
            uint32_t sAb = sA[tt & 1];
            uint32_t sBb = sBbase + (tt % 3) * SM1_BST;
            #pragma unroll
            for (int ks = 0; ks < 2; ++ks) {
                uint32_t af[4][4], bf[4][2];
                #pragma unroll
                for (int mi = 0; mi < 4; ++mi)
                    LDSM4(af[mi][0], af[mi][1], af[mi][2], af[mi][3],
                          sAb + aBase + mi * 16 * PADB + ks * 32);
                #pragma unroll
                for (int ni2 = 0; ni2 < 2; ++ni2) {
                    uint32_t r0, r1, r2, r3;
                    LDSM4(r0, r1, r2, r3, sBb + bBase + ni2 * 16 * PADB + ks * 32);
                    bf[ni2 * 2][0] = r0; bf[ni2 * 2][1] = r1;
                    bf[ni2 * 2 + 1][0] = r2; bf[ni2 * 2 + 1][1] = r3;
                }
                #pragma unroll
                for (int mi = 0; mi < 4; ++mi)
                    #pragma unroll
                    for (int ni = 0; ni < 4; ++ni)
                        MMAF16(acc[mi][ni], af[mi], bf[ni]);
            }
        }
        if (tt + 1 < NT1 && t < 256) {
            G1_APROC((tt + 1) & 1, tt + 1, q);
        }
        if (tt + 2 < NT1) { CP_WAIT1(); }
        else if (tt + 1 < NT1) { CP_WAIT0(); }
        __syncthreads();
    }

    // LN stats: 2 staging threads per row
    if (t < 256) {
        s0  += __shfl_xor_sync(0xffffffffu, s0, 1);
        s20 += __shfl_xor_sync(0xffffffffu, s20, 1);
        sg0 += __shfl_xor_sync(0xffffffffu, sg0, 1);
        if (h == 0) {
            float C0 = g_consts[0], C1 = g_consts[1];
            float mean = s0 * (1.f / Dk);
            float var = s20 * (1.f / Dk) - mean * mean;
            float rstd = rsqrtf(var + 1e-5f);
            s_rstd[lr] = rstd;
            s_nmr[lr] = -mean * rstd;
            g_feat[rowBase + lr] = (sg0 - mean * C0) * rstd * (1.f / Dk) + C1 * (1.f / Dk);
        }
    }
    __syncthreads();

    // epilogue -> g_U (fp16)
    #pragma unroll
    for (int ni = 0; ni < 4; ++ni) {
        int cg = n0w + ni * 8 + 2 * tg;
        float ca0 = g_cA[cg], ca1 = g_cA[cg + 1];
        float cb0 = g_cB[cg], cb1 = g_cB[cg + 1];
        #pragma unroll
        for (int mi = 0; mi < 4; ++mi) {
            int r1 = m0w + mi * 16 + g;
            float rs1 = s_rstd[r1], nm1 = s_nmr[r1];
            float rs2 = s_rstd[r1 + 8], nm2 = s_nmr[r1 + 8];
            uint32_t o1 = h2pack(acc[mi][ni][0] * rs1 + nm1 * ca0 + cb0,
                                 acc[mi][ni][1] * rs1 + nm1 * ca1 + cb1);
            uint32_t o2 = h2pack(acc[mi][ni][2] * rs2 + nm2 * ca0 + cb0,
                                 acc[mi][ni][3] * rs2 + nm2 * ca1 + cb1);
            *(uint32_t*)(g_U + (size_t)(rowBase + r1) * Rk + cg) = o1;
            *(uint32_t*)(g_U + (size_t)(rowBase + r1 + 8) * Rk + cg) = o2;
        }
    }
}

// ================= fp16 mma GEMM 2 — R5 version (128-col, 256-thr) ==============
#define NT2 8
#define SM2_STAGE 20480
#define SM2_TOTAL 61440

__global__ __launch_bounds__(256) void kGemm2MMA(const float* __restrict__ bq,
                                                 float* __restrict__ out) {
    extern __shared__ char sm2[];
    int t = threadIdx.x, w = t >> 5, lane = t & 31, g = lane >> 2, tg = lane & 3;
    int rowBase = blockIdx.y * 128, colBase = blockIdx.x * 128;
    int m0w = (w >> 2) * 64, n0w = (w & 3) * 32;

    uint32_t sBase0 = smem_u32(sm2);
    uint32_t aBase = (uint32_t)((m0w + (lane & 15)) * PADB + (lane >> 4) * 16);
    uint32_t bBase = 10240u + (uint32_t)((n0w + (lane & 7) + ((lane >> 4) << 3)) * PADB
                                         + ((lane >> 3) & 1) * 16);

    int lr = t >> 1, h = t & 1;
    const __half* Asrc = g_U + (size_t)(rowBase + lr) * Rk + h * 16;
    const __half* Bsrc = g_WqT + (size_t)(colBase + lr) * Rk + h * 16;

    float acc[4][4][4] = {};

    #define G2_ISSUE(st, tt) do { \
        __half* A = (__half*)(sm2 + (st) * SM2_STAGE); \
        __half* B = (__half*)(sm2 + (st) * SM2_STAGE + 10240); \
        cp16(A + lr * PADH + h * 16,     Asrc + (tt) * 32); \
        cp16(A + lr * PADH + h * 16 + 8, Asrc + (tt) * 32 + 8); \
        cp16(B + lr * PADH + h * 16,     Bsrc + (tt) * 32); \
        cp16(B + lr * PADH + h * 16 + 8, Bsrc + (tt) * 32 + 8); \
        CP_COMMIT(); \
    } while (0)

    G2_ISSUE(0, 0);
    G2_ISSUE(1, 1);
    CP_WAIT1();
    __syncthreads();

    #pragma unroll 1
    for (int tt = 0; tt < NT2; ++tt) {
        int st = tt % 3;
        uint32_t sb = sBase0 + st * SM2_STAGE;
        #pragma unroll
        for (int ks = 0; ks < 2; ++ks) {
            uint32_t af[4][4], bf[4][2];
            #pragma unroll
            for (int mi = 0; mi < 4; ++mi)
                LDSM4(af[mi][0], af[mi][1], af[mi][2], af[mi][3],
                      sb + aBase + mi * 16 * PADB + ks * 32);
            #pragma unroll
            for (int ni2 = 0; ni2 < 2; ++ni2) {
                uint32_t r0, r1, r2, r3;
                LDSM4(r0, r1, r2, r3, sb + bBase + ni2 * 16 * PADB + ks * 32);
                bf[ni2 * 2][0] = r0; bf[ni2 * 2][1] = r1;
                bf[ni2 * 2 + 1][0] = r2; bf[ni2 * 2 + 1][1] = r3;
            }
            #pragma unroll
            for (int mi = 0; mi < 4; ++mi)
                #pragma unroll
                for (int ni = 0; ni < 4; ++ni)
                    MMAF16(acc[mi][ni], af[mi], bf[ni]);
        }
        if (tt + 2 < NT2) {
            G2_ISSUE((tt + 2) % 3, tt + 2);
            CP_WAIT1();
        } else if (tt + 1 < NT2) {
            CP_WAIT0();
        }
        __syncthreads();
    }

    #pragma unroll
    for (int ni = 0; ni < 4; ++ni) {
        int cg = colBase + n0w + ni * 8 + 2 * tg;
        float G0 = g_G[cg], G1 = g_G[cg + 1];
        float q0 = bq[cg], q1 = bq[cg + 1];
        #pragma unroll
        for (int mi = 0; mi < 4; ++mi) {
            int r1 = rowBase + m0w + mi * 16 + g;
            float2 o1, o2;
            o1.x = G0 * (acc[mi][ni][0] + q0);
            o1.y = G1 * (acc[mi][ni][1] + q1);
            o2.x = G0 * (acc[mi][ni][2] + q0);
            o2.y = G1 * (acc[mi][ni][3] + q1);
            *(float2*)&out[(size_t)r1 * Dk + cg] = o1;
            *(float2*)&out[(size_t)(r1 + 8) * Dk + cg] = o2;
        }
    }
}

// ---------------- launch ----------------
extern "C" void kernel_launch(void* const* d_in, const int* in_sizes, int n_in,
                              void* d_out, int out_size) {
    const float* x     = (const float*)d_in[0];
    const float* gamma = (const float*)d_in[1];
    const float* beta  = (const float*)d_in[2];
    const float* P     = (const float*)d_in[3];
    const float* dlt   = (const float*)d_in[4];
    const float* phiw  = (const float*)d_in[5];
    const float* phib  = (const float*)d_in[6];
    const float* toep  = (const float*)d_in[7];
    const float* Wq    = (const float*)d_in[8];
    const float* bq    = (const float*)d_in[9];
    const float* glog  = (const float*)d_in[10];
    const int*   step  = (const int*)d_in[11];
    int Kc   = in_sizes[7];
    int glen = in_sizes[10];

    cudaFuncSetAttribute(kApMMA,    cudaFuncAttributeMaxDynamicSharedMemorySize, SMA_TOTAL);
    cudaFuncSetAttribute(kGemm1MMA, cudaFuncAttributeMaxDynamicSharedMemorySize, SM1_TOTAL);
    cudaFuncSetAttribute(kGemm2MMA, cudaFuncAttributeMaxDynamicSharedMemorySize, SM2_TOTAL);

    kPre1<<<865, 256>>>(gamma, beta, phiw, P, toep, Wq, Kc);
    kEg<<<33, 256>>>(dlt);
    kApMMA<<<288, 256, SMA_TOTAL>>>(gamma);
    kGemm1MMA<<<128, 512, SM1_TOTAL>>>(x, gamma);
    kScale<<<256, 256>>>(phib, glog, step, glen);
    kGemm2MMA<<<dim3(16, 128), 256, SM2_TOTAL>>>(bq, (float*)d_out);
}

// round 14
// speedup vs baseline: 1.2150x; 1.0040x over previous
#include <cuda_runtime.h>
#include <cuda_fp16.h>
#include <cstdint>
#include <math.h>

#define Bk 8
#define Lk 2048
#define Dk 2048
#define Rk 256
#define BLk (Bk * Lk)   // 16384 rows

// ---------------- device scratch ----------------
static __device__ float g_E[Rk * Rk];                 // E = C @ dlt fp32  (256x256)
static __device__ __half g_Eh[Rk * Rk];               // E fp16
static __device__ __half g_Ph[Dk * Rk];               // P fp16 (d-major, r-contig)
static __device__ __half g_BT1[Rk * Dk];              // A'^T fp16         (256x2048)
static __device__ __half g_WqT[Dk * Rk];              // Wq^T fp16         (2048x256)
static __device__ __half g_U[(size_t)BLk * Rk];       // z_mixed fp16
static __device__ float g_feat[BLk];
static __device__ float g_pg[Rk], g_pb[Rk];
static __device__ float g_cA[Rk], g_cB[Rk];
static __device__ float g_G[Dk];
static __device__ float g_consts[4];
static __device__ float g_pgp[32 * Rk], g_pbp[32 * Rk];

// ---------------- helpers ----------------
__device__ __forceinline__ uint32_t smem_u32(const void* p) {
    uint32_t a;
    asm("{ .reg .u64 t; cvta.to.shared.u64 t, %1; cvt.u32.u64 %0, t; }" : "=r"(a) : "l"(p));
    return a;
}
__device__ __forceinline__ void cp16(void* dst, const void* src) {
    uint32_t d = smem_u32(dst);
    asm volatile("cp.async.cg.shared.global [%0], [%1], 16;" :: "r"(d), "l"(src) : "memory");
}
#define CP_COMMIT() asm volatile("cp.async.commit_group;" ::: "memory")
#define CP_WAIT0()  asm volatile("cp.async.wait_group 0;" ::: "memory")
#define CP_WAIT1()  asm volatile("cp.async.wait_group 1;" ::: "memory")

#define LDSM4(r0, r1, r2, r3, addr) \
    asm volatile("ldmatrix.sync.aligned.m8n8.x4.shared.b16 {%0,%1,%2,%3}, [%4];" \
        : "=r"(r0), "=r"(r1), "=r"(r2), "=r"(r3) : "r"(addr))

#define MMAF16(c, a, b) \
    asm volatile( \
        "mma.sync.aligned.m16n8k16.row.col.f32.f16.f16.f32 " \
        "{%0,%1,%2,%3},{%4,%5,%6,%7},{%8,%9},{%0,%1,%2,%3};" \
        : "+f"((c)[0]), "+f"((c)[1]), "+f"((c)[2]), "+f"((c)[3]) \
        : "r"((a)[0]), "r"((a)[1]), "r"((a)[2]), "r"((a)[3]), \
          "r"((b)[0]), "r"((b)[1]))

__device__ __forceinline__ uint32_t h2pack(float a, float b) {
    __half2 h = __floats2half2_rn(a, b);
    return *reinterpret_cast<uint32_t*>(&h);
}

__device__ __forceinline__ float blockReduce256(float v, float* sm) {
    int t = threadIdx.x;
    sm[t] = v;
    __syncthreads();
    #pragma unroll
    for (int off = 128; off > 0; off >>= 1) {
        if (t < off) sm[t] += sm[t + off];
        __syncthreads();
    }
    float r = sm[0];
    __syncthreads();
    return r;
}

// pad-40-halves row layout (80 bytes): ldmatrix phases conflict-free.
#define PADH 40
#define PADB 80

// ================= fused precompute 1 =================
// bid 0: consts; 1..32: pgb partials; 33..544: WqT transpose; 545..608: Ph
__global__ __launch_bounds__(256) void kPre1(const float* __restrict__ gamma,
                                             const float* __restrict__ beta,
                                             const float* __restrict__ phiw,
                                             const float* __restrict__ P,
                                             const float* __restrict__ Wq) {
    int bid = blockIdx.x, t = threadIdx.x;
    if (bid == 0) {
        __shared__ float sm[256];
        float a = 0.f, b = 0.f, c = 0.f;
        for (int j = t; j < Dk; j += 256) { a += gamma[j]; b += beta[j]; }
        for (int j = t; j < Rk; j += 256) { c += phiw[j]; }
        float A = blockReduce256(a, sm);
        float B = blockReduce256(b, sm);
        float C = blockReduce256(c, sm);
        if (t == 0) { g_consts[0] = A; g_consts[1] = B; g_consts[2] = C; }
    } else if (bid <= 32) {
        int chunk = bid - 1;
        float ag = 0.f, ab = 0.f;
        #pragma unroll 4
        for (int j = 0; j < 64; j++) {
            int d = chunk * 64 + j;
            float p = P[(size_t)d * Rk + t];
            ag += gamma[d] * p;
            ab += beta[d] * p;
        }
        g_pgp[chunk * Rk + t] = ag;
        g_pbp[chunk * Rk + t] = ab;
    } else if (bid <= 544) {
        int id = bid - 33;
        int bx = id & 63, by = id >> 6;
        __shared__ float tile[32][33];
        int tx = t & 31, ty8 = t >> 5;
        #pragma unroll
        for (int i = 0; i < 32; i += 8)
            tile[ty8 + i][tx] = Wq[(size_t)(by * 32 + ty8 + i) * Dk + bx * 32 + tx];
        __syncthreads();
        #pragma unroll
        for (int i = 0; i < 32; i += 8)
            g_WqT[(size_t)(bx * 32 + ty8 + i) * Rk + by * 32 + tx] =
                __float2half_rn(tile[tx][ty8 + i]);
    } else {
        // Ph = fp16(P): 64 blocks x 8192 elems
        int base = (bid - 545) * 8192;
        #pragma unroll
        for (int i = 0; i < 8; i++) {
            int idx = base + i * 1024 + t * 4;
            float4 v = *(const float4*)&P[idx];
            uint2 pk = { h2pack(v.x, v.y), h2pack(v.z, v.w) };
            *(uint2*)&g_Ph[idx] = pk;
        }
    }
}

// ================= kEg: E = C @ dlt (C inline from toep) + pgb2 ================
// 32x64 tiles, grid 33. C[s,i] = toep[i-s+pad] (0 outside range).
__global__ __launch_bounds__(256) void kEg(const float* __restrict__ dlt,
                                           const float* __restrict__ toep, int Kc) {
    int bid = blockIdx.x, t = threadIdx.x;
    if (bid == 32) {
        float a = 0.f, b = 0.f;
        #pragma unroll
        for (int c = 0; c < 32; c++) { a += g_pgp[c * Rk + t]; b += g_pbp[c * Rk + t]; }
        g_pg[t] = a;
        g_pb[t] = b;
        return;
    }
    __shared__ float st[256];
    __shared__ float Cs[16][34];
    __shared__ float Ds[16][68];
    if (t < Kc) st[t] = toep[t];
    else if (t < 256) st[t] = 0.f;
    int bx = bid & 3, by = bid >> 2;
    int sBase = by * 32, rBase = bx * 64;
    int ty = t >> 4, tx = t & 15;
    int pad = (Kc - 1) >> 1;
    float acc[2][4] = {};
    __syncthreads();
    for (int k0 = 0; k0 < Rk; k0 += 16) {
        {
            int m = t >> 3, kq = (t & 7) * 2;
            int s = sBase + m;
            int i0 = k0 + kq;
            int idx0 = i0 - s + pad, idx1 = idx0 + 1;
            Cs[kq][m]     = ((unsigned)idx0 < (unsigned)Kc) ? st[idx0] : 0.f;
            Cs[kq + 1][m] = ((unsigned)idx1 < (unsigned)Kc) ? st[idx1] : 0.f;
        }
        {
            int kk = t >> 4, n4 = (t & 15) * 4;
            float4 v = *(const float4*)&dlt[(size_t)(k0 + kk) * Rk + rBase + n4];
            *(float4*)&Ds[kk][n4] = v;
        }
        __syncthreads();
        #pragma unroll
        for (int k = 0; k < 16; k++) {
            float a0 = Cs[k][ty * 2], a1 = Cs[k][ty * 2 + 1];
            float b[4];
            #pragma unroll
            for (int j = 0; j < 4; j++) b[j] = Ds[k][tx * 4 + j];
            #pragma unroll
            for (int j = 0; j < 4; j++) { acc[0][j] += a0 * b[j]; acc[1][j] += a1 * b[j]; }
        }
        __syncthreads();
    }
    #pragma unroll
    for (int i = 0; i < 2; i++) {
        int s = sBase + ty * 2 + i;
        #pragma unroll
        for (int j = 0; j < 4; j++) {
            int r = rBase + tx * 4 + j;
            g_E[(size_t)s * Rk + r] = acc[i][j];
            g_Eh[(size_t)s * Rk + r] = __float2half_rn(acc[i][j]);
        }
    }
}

// ================= kApMMA: BT1[s][d] = fp16(gamma[d] * (Eh @ Ph^T)) + cA/cB =====
// bid < 32: mma tile. bid 32..63: cA/cB, warp per s (8 s per block).
#define NTA 8
#define SMA_STAGE 20480
#define SMA_TOTAL 61440

__global__ __launch_bounds__(256) void kApMMA(const float* __restrict__ gamma) {
    extern __shared__ char sma[];
    int bid = blockIdx.x, t = threadIdx.x;
    int w = t >> 5, lane = t & 31;
    if (bid >= 32) {
        int s = (bid - 32) * 8 + w;
        float ca = 0.f, cb = 0.f;
        #pragma unroll
        for (int j = 0; j < 8; j++) {
            int r = lane + 32 * j;
            float e = g_E[(size_t)s * Rk + r];
            ca += g_pg[r] * e;
            cb += g_pb[r] * e;
        }
        #pragma unroll
        for (int o = 16; o > 0; o >>= 1) {
            ca += __shfl_xor_sync(0xffffffffu, ca, o);
            cb += __shfl_xor_sync(0xffffffffu, cb, o);
        }
        if (lane == 0) { g_cA[s] = ca; g_cB[s] = cb; }
        return;
    }
    int g = lane >> 2, tg = lane & 3;
    int rowBase = (bid >> 4) * 128;   // s
    int colBase = (bid & 15) * 128;   // d
    int m0w = (w >> 2) * 64, n0w = (w & 3) * 32;

    uint32_t sBase0 = smem_u32(sma);
    uint32_t aBase = (uint32_t)((m0w + (lane & 15)) * PADB + (lane >> 4) * 16);
    uint32_t bBase = 10240u + (uint32_t)((n0w + (lane & 7) + ((lane >> 4) << 3)) * PADB
                                         + ((lane >> 3) & 1) * 16);

    int lr = t >> 1, h = t & 1;
    const __half* Asrc = g_Eh + (size_t)(rowBase + lr) * Rk + h * 16;
    const __half* Bsrc = g_Ph + (size_t)(colBase + lr) * Rk + h * 16;

    float acc[4][4][4] = {};

    #define GA_ISSUE(st, tt) do { \
        __half* A = (__half*)(sma + (st) * SMA_STAGE); \
        __half* B = (__half*)(sma + (st) * SMA_STAGE + 10240); \
        cp16(A + lr * PADH + h * 16,     Asrc + (tt) * 32); \
        cp16(A + lr * PADH + h * 16 + 8, Asrc + (tt) * 32 + 8); \
        cp16(B + lr * PADH + h * 16,     Bsrc + (tt) * 32); \
        cp16(B + lr * PADH + h * 16 + 8, Bsrc + (tt) * 32 + 8); \
        CP_COMMIT(); \
    } while (0)

    GA_ISSUE(0, 0);
    GA_ISSUE(1, 1);
    CP_WAIT1();
    __syncthreads();

    #pragma unroll 1
    for (int tt = 0; tt < NTA; ++tt) {
        int st = tt % 3;
        uint32_t sb = sBase0 + st * SMA_STAGE;
        #pragma unroll
        for (int ks = 0; ks < 2; ++ks) {
            uint32_t af[4][4], bf[4][2];
            #pragma unroll
            for (int mi = 0; mi < 4; ++mi)
                LDSM4(af[mi][0], af[mi][1], af[mi][2], af[mi][3],
                      sb + aBase + mi * 16 * PADB + ks * 32);
            #pragma unroll
            for (int ni2 = 0; ni2 < 2; ++ni2) {
                uint32_t r0, r1, r2, r3;
                LDSM4(r0, r1, r2, r3, sb + bBase + ni2 * 16 * PADB + ks * 32);
                bf[ni2 * 2][0] = r0; bf[ni2 * 2][1] = r1;
                bf[ni2 * 2 + 1][0] = r2; bf[ni2 * 2 + 1][1] = r3;
            }
            #pragma unroll
            for (int mi = 0; mi < 4; ++mi)
                #pragma unroll
                for (int ni = 0; ni < 4; ++ni)
                    MMAF16(acc[mi][ni], af[mi], bf[ni]);
        }
        if (tt + 2 < NTA) {
            GA_ISSUE((tt + 2) % 3, tt + 2);
            CP_WAIT1();
        } else if (tt + 1 < NTA) {
            CP_WAIT0();
        }
        __syncthreads();
    }

    #pragma unroll
    for (int ni = 0; ni < 4; ++ni) {
        int cg = colBase + n0w + ni * 8 + 2 * tg;
        float ga0 = gamma[cg], ga1 = gamma[cg + 1];
        #pragma unroll
        for (int mi = 0; mi < 4; ++mi) {
            int s1 = rowBase + m0w + mi * 16 + g;
            *(uint32_t*)&g_BT1[(size_t)s1 * Dk + cg] =
                h2pack(ga0 * acc[mi][ni][0], ga1 * acc[mi][ni][1]);
            *(uint32_t*)&g_BT1[(size_t)(s1 + 8) * Dk + cg] =
                h2pack(ga0 * acc[mi][ni][2], ga1 * acc[mi][ni][3]);
        }
    }
}

// G[l] = sigmoid(g_logit[..]) * scale[l]  (needs g_feat from GEMM1)
__global__ void kScale(const float* __restrict__ phib, const float* __restrict__ glog,
                       const int* __restrict__ step_p, int glen) {
    int w = threadIdx.x >> 5, lane = threadIdx.x & 31;
    int l = blockIdx.x * 8 + w;
    const float PI_F = 3.14159274101257324f;
    float base = PI_F * ((float)l + 0.5f);
    float c1 = 0.f, c2 = 0.f;
    #pragma unroll
    for (int j = 0; j < 8; j++) {
        int r = lane + 32 * j;
        c1 += cosf((base * (float)r) / (float)Lk);
        c2 += phib[(size_t)l * Rk + r];
    }
    float c3 = (lane < Bk) ? g_feat[(size_t)lane * Lk + l] : 0.f;
    #pragma unroll
    for (int o = 16; o > 0; o >>= 1) {
        c1 += __shfl_xor_sync(0xffffffffu, c1, o);
        c2 += __shfl_xor_sync(0xffffffffu, c2, o);
        c3 += __shfl_xor_sync(0xffffffffu, c3, o);
    }
    if (lane == 0) {
        int step = *step_p;
        float det_scale = fminf((float)((double)step / 2000.0), 1.0f);
        float scale = det_scale * (c1 / (float)Rk) + (c2 / (float)Rk)
                    + (c3 / (float)Bk) * (g_consts[2] / (float)Rk);
        int gi = l / (Dk / glen);
        float gs = 1.0f / (1.0f + expf(-glog[gi]));
        g_G[l] = gs * scale;
    }
}

// ================= fp16 mma GEMM 1 — R13 version =================
#define NT1 64
#define SM1_AS0   0
#define SM1_AS1   10240
#define SM1_BS    20480   // 3 stages x 20480
#define SM1_BST   20480
#define SM1_GAM   81920
#define SM1_RSTD  90112
#define SM1_NMR   90624
#define SM1_TOTAL 91136

__global__ __launch_bounds__(512) void kGemm1MMA(const float* __restrict__ X,
                                                 const float* __restrict__ gamma) {
    extern __shared__ char sm1[];
    __half* As[2] = { (__half*)(sm1 + SM1_AS0), (__half*)(sm1 + SM1_AS1) };
    float* s_gam  = (float*)(sm1 + SM1_GAM);
    float* s_rstd = (float*)(sm1 + SM1_RSTD);
    float* s_nmr  = (float*)(sm1 + SM1_NMR);

    int t = threadIdx.x, w = t >> 5, lane = t & 31, g = lane >> 2, tg = lane & 3;
    int rowBase = blockIdx.x * 128;
    int m0w = (w >> 3) * 64, n0w = (w & 7) * 32;

    for (int i = t; i < Dk / 4; i += 512)
        ((float4*)s_gam)[i] = ((const float4*)gamma)[i];

    uint32_t sA[2] = { smem_u32(As[0]), smem_u32(As[1]) };
    uint32_t sBbase = smem_u32(sm1 + SM1_BS);
    uint32_t aBase = (uint32_t)((m0w + (lane & 15)) * PADB + (lane >> 4) * 16);
    uint32_t bBase = (uint32_t)((n0w + (lane & 7) + ((lane >> 4) << 3)) * PADB
                                + ((lane >> 3) & 1) * 16);

    int lr = t >> 1, h = t & 1;   // A stagers: row (0..127), 16-float half
    int t2 = t & 255;             // B stagers row
    const float4* Xr = (const float4*)(X + (size_t)(rowBase + lr) * Dk);
    const __half* Bsrc = g_BT1 + (size_t)t2 * Dk;

    float acc[4][4][4] = {};
    float s0 = 0.f, s20 = 0.f, sg0 = 0.f;

    __syncthreads();  // gamma visible

    #define G1_APROC(st, tt, q) do { \
        _Pragma("unroll") \
        for (int j = 0; j < 4; j++) { \
            float4 gv = ((const float4*)s_gam)[(tt) * 8 + h * 4 + j]; \
            s0  += (q[j].x + q[j].y) + (q[j].z + q[j].w); \
            s20 += q[j].x*q[j].x + q[j].y*q[j].y + q[j].z*q[j].z + q[j].w*q[j].w; \
            sg0 += gv.x*q[j].x + gv.y*q[j].y + gv.z*q[j].z + gv.w*q[j].w; \
        } \
        uint4 p0 = { h2pack(q[0].x,q[0].y), h2pack(q[0].z,q[0].w), \
                     h2pack(q[1].x,q[1].y), h2pack(q[1].z,q[1].w) }; \
        uint4 p1 = { h2pack(q[2].x,q[2].y), h2pack(q[2].z,q[2].w), \
                     h2pack(q[3].x,q[3].y), h2pack(q[3].z,q[3].w) }; \
        *(uint4*)(As[(st)] + lr * PADH + h * 16)     = p0; \
        *(uint4*)(As[(st)] + lr * PADH + h * 16 + 8) = p1; \
    } while (0)

    #define G1_BISSUE(st, tt) do { \
        __half* B = (__half*)(sm1 + SM1_BS + (st) * SM1_BST); \
        const __half* src = Bsrc + (tt) * 32; \
        cp16(B + t2 * PADH + 0,  src); \
        cp16(B + t2 * PADH + 8,  src + 8); \
        cp16(B + t2 * PADH + 16, src + 16); \
        cp16(B + t2 * PADH + 24, src + 24); \
        CP_COMMIT(); \
    } while (0)

    // prologue: A tile0 -> As[0]; B tiles 0,1 -> stages 0,1
    if (t >= 256) {
        G1_BISSUE(0, 0);
        G1_BISSUE(1, 1);
    } else {
        float4 q[4];
        #pragma unroll
        for (int j = 0; j < 4; j++) q[j] = Xr[h * 4 + j];
        G1_APROC(0, 0, q);
    }
    CP_WAIT1();
    __syncthreads();

    #pragma unroll 1
    for (int tt = 0; tt < NT1; ++tt) {
        float4 q[4];
        if (t >= 256) {
            if (tt + 2 < NT1) G1_BISSUE((tt + 2) % 3, tt + 2);
        } else if (tt + 1 < NT1) {
            int kq = (tt + 1) * 8;
            #pragma unroll
            for (int j = 0; j < 4; j++) q[j] = Xr[kq + h * 4 + j];
        }
        {
            uint32_t sAb = sA[tt & 1];
            uint32_t sBb = sBbase + (tt % 3) * SM1_BST;
            #pragma unroll
            for (int ks = 0; ks < 2; ++ks) {
                uint32_t af[4][4], bf[4][2];
                #pragma unroll
                for (int mi = 0; mi < 4; ++mi)
                    LDSM4(af[mi][0], af[mi][1], af[mi][2], af[mi][3],
                          sAb + aBase + mi * 16 * PADB + ks * 32);
                #pragma unroll
                for (int ni2 = 0; ni2 < 2; ++ni2) {
                    uint32_t r0, r1, r2, r3;
                    LDSM4(r0, r1, r2, r3, sBb + bBase + ni2 * 16 * PADB + ks * 32);
                    bf[ni2 * 2][0] = r0; bf[ni2 * 2][1] = r1;
                    bf[ni2 * 2 + 1][0] = r2; bf[ni2 * 2 + 1][1] = r3;
                }
                #pragma unroll
                for (int mi = 0; mi < 4; ++mi)
                    #pragma unroll
                    for (int ni = 0; ni < 4; ++ni)
                        MMAF16(acc[mi][ni], af[mi], bf[ni]);
            }
        }
        if (tt + 1 < NT1 && t < 256) {
            G1_APROC((tt + 1) & 1, tt + 1, q);
        }
        if (tt + 2 < NT1) { CP_WAIT1(); }
        else if (tt + 1 < NT1) { CP_WAIT0(); }
        __syncthreads();
    }

    // LN stats: 2 staging threads per row
    if (t < 256) {
        s0  += __shfl_xor_sync(0xffffffffu, s0, 1);
        s20 += __shfl_xor_sync(0xffffffffu, s20, 1);
        sg0 += __shfl_xor_sync(0xffffffffu, sg0, 1);
        if (h == 0) {
            float C0 = g_consts[0], C1 = g_consts[1];
            float mean = s0 * (1.f / Dk);
            float var = s20 * (1.f / Dk) - mean * mean;
            float rstd = rsqrtf(var + 1e-5f);
            s_rstd[lr] = rstd;
            s_nmr[lr] = -mean * rstd;
            g_feat[rowBase + lr] = (sg0 - mean * C0) * rstd * (1.f / Dk) + C1 * (1.f / Dk);
        }
    }
    __syncthreads();

    // epilogue -> g_U (fp16)
    #pragma unroll
    for (int ni = 0; ni < 4; ++ni) {
        int cg = n0w + ni * 8 + 2 * tg;
        float ca0 = g_cA[cg], ca1 = g_cA[cg + 1];
        float cb0 = g_cB[cg], cb1 = g_cB[cg + 1];
        #pragma unroll
        for (int mi = 0; mi < 4; ++mi) {
            int r1 = m0w + mi * 16 + g;
            float rs1 = s_rstd[r1], nm1 = s_nmr[r1];
            float rs2 = s_rstd[r1 + 8], nm2 = s_nmr[r1 + 8];
            uint32_t o1 = h2pack(acc[mi][ni][0] * rs1 + nm1 * ca0 + cb0,
                                 acc[mi][ni][1] * rs1 + nm1 * ca1 + cb1);
            uint32_t o2 = h2pack(acc[mi][ni][2] * rs2 + nm2 * ca0 + cb0,
                                 acc[mi][ni][3] * rs2 + nm2 * ca1 + cb1);
            *(uint32_t*)(g_U + (size_t)(rowBase + r1) * Rk + cg) = o1;
            *(uint32_t*)(g_U + (size_t)(rowBase + r1 + 8) * Rk + cg) = o2;
        }
    }
}

// ================= fp16 mma GEMM 2 — R5 version (128-col, 256-thr) ==============
#define NT2 8
#define SM2_STAGE 20480
#define SM2_TOTAL 61440

__global__ __launch_bounds__(256) void kGemm2MMA(const float* __restrict__ bq,
                                                 float* __restrict__ out) {
    extern __shared__ char sm2[];
    int t = threadIdx.x, w = t >> 5, lane = t & 31, g = lane >> 2, tg = lane & 3;
    int rowBase = blockIdx.y * 128, colBase = blockIdx.x * 128;
    int m0w = (w >> 2) * 64, n0w = (w & 3) * 32;

    uint32_t sBase0 = smem_u32(sm2);
    uint32_t aBase = (uint32_t)((m0w + (lane & 15)) * PADB + (lane >> 4) * 16);
    uint32_t bBase = 10240u + (uint32_t)((n0w + (lane & 7) + ((lane >> 4) << 3)) * PADB
                                         + ((lane >> 3) & 1) * 16);

    int lr = t >> 1, h = t & 1;
    const __half* Asrc = g_U + (size_t)(rowBase + lr) * Rk + h * 16;
    const __half* Bsrc = g_WqT + (size_t)(colBase + lr) * Rk + h * 16;

    float acc[4][4][4] = {};

    #define G2_ISSUE(st, tt) do { \
        __half* A = (__half*)(sm2 + (st) * SM2_STAGE); \
        __half* B = (__half*)(sm2 + (st) * SM2_STAGE + 10240); \
        cp16(A + lr * PADH + h * 16,     Asrc + (tt) * 32); \
        cp16(A + lr * PADH + h * 16 + 8, Asrc + (tt) * 32 + 8); \
        cp16(B + lr * PADH + h * 16,     Bsrc + (tt) * 32); \
        cp16(B + lr * PADH + h * 16 + 8, Bsrc + (tt) * 32 + 8); \
        CP_COMMIT(); \
    } while (0)

    G2_ISSUE(0, 0);
    G2_ISSUE(1, 1);
    CP_WAIT1();
    __syncthreads();

    #pragma unroll 1
    for (int tt = 0; tt < NT2; ++tt) {
        int st = tt % 3;
        uint32_t sb = sBase0 + st * SM2_STAGE;
        #pragma unroll
        for (int ks = 0; ks < 2; ++ks) {
            uint32_t af[4][4], bf[4][2];
            #pragma unroll
            for (int mi = 0; mi < 4; ++mi)
                LDSM4(af[mi][0], af[mi][1], af[mi][2], af[mi][3],
                      sb + aBase + mi * 16 * PADB + ks * 32);
            #pragma unroll
            for (int ni2 = 0; ni2 < 2; ++ni2) {
                uint32_t r0, r1, r2, r3;
                LDSM4(r0, r1, r2, r3, sb + bBase + ni2 * 16 * PADB + ks * 32);
                bf[ni2 * 2][0] = r0; bf[ni2 * 2][1] = r1;
                bf[ni2 * 2 + 1][0] = r2; bf[ni2 * 2 + 1][1] = r3;
            }
            #pragma unroll
            for (int mi = 0; mi < 4; ++mi)
                #pragma unroll
                for (int ni = 0; ni < 4; ++ni)
                    MMAF16(acc[mi][ni], af[mi], bf[ni]);
        }
        if (tt + 2 < NT2) {
            G2_ISSUE((tt + 2) % 3, tt + 2);
            CP_WAIT1();
        } else if (tt + 1 < NT2) {
            CP_WAIT0();
        }
        __syncthreads();
    }

    #pragma unroll
    for (int ni = 0; ni < 4; ++ni) {
        int cg = colBase + n0w + ni * 8 + 2 * tg;
        float G0 = g_G[cg], G1 = g_G[cg + 1];
        float q0 = bq[cg], q1 = bq[cg + 1];
        #pragma unroll
        for (int mi = 0; mi < 4; ++mi) {
            int r1 = rowBase + m0w + mi * 16 + g;
            float2 o1, o2;
            o1.x = G0 * (acc[mi][ni][0] + q0);
            o1.y = G1 * (acc[mi][ni][1] + q1);
            o2.x = G0 * (acc[mi][ni][2] + q0);
            o2.y = G1 * (acc[mi][ni][3] + q1);
            *(float2*)&out[(size_t)r1 * Dk + cg] = o1;
            *(float2*)&out[(size_t)(r1 + 8) * Dk + cg] = o2;
        }
    }
}

// ---------------- launch ----------------
extern "C" void kernel_launch(void* const* d_in, const int* in_sizes, int n_in,
                              void* d_out, int out_size) {
    const float* x     = (const float*)d_in[0];
    const float* gamma = (const float*)d_in[1];
    const float* beta  = (const float*)d_in[2];
    const float* P     = (const float*)d_in[3];
    const float* dlt   = (const float*)d_in[4];
    const float* phiw  = (const float*)d_in[5];
    const float* phib  = (const float*)d_in[6];
    const float* toep  = (const float*)d_in[7];
    const float* Wq    = (const float*)d_in[8];
    const float* bq    = (const float*)d_in[9];
    const float* glog  = (const float*)d_in[10];
    const int*   step  = (const int*)d_in[11];
    int Kc   = in_sizes[7];
    int glen = in_sizes[10];

    cudaFuncSetAttribute(kApMMA,    cudaFuncAttributeMaxDynamicSharedMemorySize, SMA_TOTAL);
    cudaFuncSetAttribute(kGemm1MMA, cudaFuncAttributeMaxDynamicSharedMemorySize, SM1_TOTAL);
    cudaFuncSetAttribute(kGemm2MMA, cudaFuncAttributeMaxDynamicSharedMemorySize, SM2_TOTAL);

    kPre1<<<609, 256>>>(gamma, beta, phiw, P, Wq);
    kEg<<<33, 256>>>(dlt, toep, Kc);
    kApMMA<<<64, 256, SMA_TOTAL>>>(gamma);
    kGemm1MMA<<<128, 512, SM1_TOTAL>>>(x, gamma);
    kScale<<<256, 256>>>(phib, glog, step, glen);
    kGemm2MMA<<<dim3(16, 128), 256, SM2_TOTAL>>>(bq, (float*)d_out);
}